// round 1
// baseline (speedup 1.0000x reference)
#include <cuda_runtime.h>
#include <cuda_bf16.h>
#include <math.h>
#include <stdint.h>

#define MAXN 8192
#define FDIM 128
#define HDIM 512

#define XS_STRIDE 68   // 64 rows + pad (floats); 272B, 16B-aligned rows
#define WS_STRIDE 132  // 128 cols + pad; 528B
#define HC_STRIDE 136  // 128 kk + pad; 544B, 136%32=8 -> only 4-way store conflicts

typedef unsigned long long ull;

// ---------------- device scratch (static: no allocations allowed) ----------
__device__ float g_E[3 * MAXN * FDIM];     // filtered embeddings, 12.6 MB
__device__ float g_lt[MAXN];               // triplet losses
__device__ ull   g_key[MAXN];              // (user<<17)|(pos<<1)|ind
__device__ float g_l2sum;
__device__ float g_ltw;

// ---------------- packed f32x2 helpers (Blackwell sm_100+) -----------------
__device__ __forceinline__ ull ffma2(ull a, ull b, ull c) {
    ull d;
    asm("fma.rn.f32x2 %0, %1, %2, %3;" : "=l"(d) : "l"(a), "l"(b), "l"(c));
    return d;
}
__device__ __forceinline__ ull pack2(float x, float y) {
    ull r;
    asm("mov.b64 %0, {%1, %2};" : "=l"(r) : "f"(x), "f"(y));
    return r;
}
__device__ __forceinline__ float2 unpack2(ull v) {
    float2 r;
    asm("mov.b64 {%0, %1}, %2;" : "=f"(r.x), "=f"(r.y) : "l"(v));
    return r;
}

// ===========================================================================
// Kernel A: gather + renorm + Linear/BN/LeakyReLU/Linear for all 3N rows
// Block: 256 threads, 64 rows. 4 chunks of 128 H-columns.
// ===========================================================================
extern __shared__ unsigned char s_raw[];

__global__ __launch_bounds__(256, 1)
void embed_filter_kernel(const int* __restrict__ user0, const int* __restrict__ posi,
                         const int* __restrict__ negi,
                         const float* __restrict__ ut, const float* __restrict__ it,
                         const float* __restrict__ W1, const float* __restrict__ b1,
                         const float* __restrict__ gamma1, const float* __restrict__ beta1,
                         const float* __restrict__ rmean, const float* __restrict__ rvar,
                         const float* __restrict__ W2, const float* __restrict__ b2,
                         int N)
{
    float* Xs   = (float*)s_raw;                 // [128][XS_STRIDE]  k-major X tile
    float* Ws   = Xs + FDIM * XS_STRIDE;         // [128][WS_STRIDE]  k-major W chunk
    float* Hc   = Ws + FDIM * WS_STRIDE;         // [64][HC_STRIDE]   row-major H chunk
    float* bnsc = Hc + 64 * HC_STRIDE;           // [512]
    float* bnsh = bnsc + HDIM;                   // [512]
    float* srow = bnsh + HDIM;                   // [64]

    const int tid = threadIdx.x;
    const int r0  = blockIdx.x * 64;
    const int R3  = 3 * N;

    // fold b1 and BN into scale/shift
    for (int h = tid; h < HDIM; h += 256) {
        float sc = gamma1[h] * rsqrtf(rvar[h] + 1e-5f);
        bnsc[h] = sc;
        bnsh[h] = (b1[h] - rmean[h]) * sc + beta1[h];
    }

    // gather rows (4 threads / row), compute row norms
    {
        const int lr = tid >> 2, q = tid & 3;
        const int r = r0 + lr;
        const bool valid = (r < R3);
        const float* src = ut;
        if (valid) {
            int g = r / N;
            int n = r - g * N;
            int idx = (g == 0) ? user0[n] : ((g == 1) ? posi[n] : negi[n]);
            src = ((g == 0) ? ut : it) + (size_t)idx * FDIM;
        }
        float ss = 0.f;
        #pragma unroll
        for (int j = 0; j < 8; j++) {
            int k = q * 32 + j * 4;
            float4 v = valid ? *(const float4*)(src + k) : make_float4(0.f, 0.f, 0.f, 0.f);
            ss += v.x * v.x + v.y * v.y + v.z * v.z + v.w * v.w;
            Xs[(k + 0) * XS_STRIDE + lr] = v.x;
            Xs[(k + 1) * XS_STRIDE + lr] = v.y;
            Xs[(k + 2) * XS_STRIDE + lr] = v.z;
            Xs[(k + 3) * XS_STRIDE + lr] = v.w;
        }
        ss += __shfl_xor_sync(0xffffffffu, ss, 1);
        ss += __shfl_xor_sync(0xffffffffu, ss, 2);
        if (q == 0) srow[lr] = 1.0f / fmaxf(sqrtf(ss), 1.0f);
    }
    __syncthreads();

    // renorm in place (max_norm=1 embedding renorm)
    for (int i = tid; i < FDIM * 64; i += 256) {
        int k = i >> 6, rr = i & 63;
        Xs[k * XS_STRIDE + rr] *= srow[rr];
    }

    const int rg = tid >> 4;   // row group: rows rg*4 .. rg*4+3
    const int cg = tid & 15;   // col group: cols cg*8 .. cg*8+7

    ull accE[4][4];
    #pragma unroll
    for (int i = 0; i < 4; i++)
        #pragma unroll
        for (int j = 0; j < 4; j++) accE[i][j] = 0ull;

    for (int c = 0; c < 4; c++) {
        __syncthreads();
        // stage W1 chunk transposed: Ws[k][col] = W1[c*128+col][k]
        for (int i = tid; i < FDIM * FDIM; i += 256) {
            int col = i >> 7, k = i & 127;
            Ws[k * WS_STRIDE + col] = W1[(c * FDIM + col) * FDIM + k];
        }
        __syncthreads();

        // GEMM1: H[64][128] = X @ W1c^T
        ull acc1[4][4];
        #pragma unroll
        for (int i = 0; i < 4; i++)
            #pragma unroll
            for (int j = 0; j < 4; j++) acc1[i][j] = 0ull;

        {
            const float* xp = Xs + rg * 4;
            const float* wp = Ws + cg * 8;
            #pragma unroll 4
            for (int k = 0; k < FDIM; k++) {
                float4 a = *(const float4*)(xp + k * XS_STRIDE);
                ulonglong2 bq0 = *(const ulonglong2*)(wp + k * WS_STRIDE);
                ulonglong2 bq1 = *(const ulonglong2*)(wp + k * WS_STRIDE + 4);
                ull av0 = pack2(a.x, a.x), av1 = pack2(a.y, a.y);
                ull av2 = pack2(a.z, a.z), av3 = pack2(a.w, a.w);
                ull bv0 = bq0.x, bv1 = bq0.y, bv2 = bq1.x, bv3 = bq1.y;
                acc1[0][0] = ffma2(av0, bv0, acc1[0][0]); acc1[0][1] = ffma2(av0, bv1, acc1[0][1]);
                acc1[0][2] = ffma2(av0, bv2, acc1[0][2]); acc1[0][3] = ffma2(av0, bv3, acc1[0][3]);
                acc1[1][0] = ffma2(av1, bv0, acc1[1][0]); acc1[1][1] = ffma2(av1, bv1, acc1[1][1]);
                acc1[1][2] = ffma2(av1, bv2, acc1[1][2]); acc1[1][3] = ffma2(av1, bv3, acc1[1][3]);
                acc1[2][0] = ffma2(av2, bv0, acc1[2][0]); acc1[2][1] = ffma2(av2, bv1, acc1[2][1]);
                acc1[2][2] = ffma2(av2, bv2, acc1[2][2]); acc1[2][3] = ffma2(av2, bv3, acc1[2][3]);
                acc1[3][0] = ffma2(av3, bv0, acc1[3][0]); acc1[3][1] = ffma2(av3, bv1, acc1[3][1]);
                acc1[3][2] = ffma2(av3, bv2, acc1[3][2]); acc1[3][3] = ffma2(av3, bv3, acc1[3][3]);
            }
        }
        __syncthreads();

        // BN + LeakyReLU -> Hc (row-major), and stage W2 chunk: Ws[kk][f]
        #pragma unroll
        for (int j = 0; j < 4; j++) {
            int col = cg * 8 + j * 2;
            float s0 = bnsc[c * FDIM + col],     h0 = bnsh[c * FDIM + col];
            float s1 = bnsc[c * FDIM + col + 1], h1 = bnsh[c * FDIM + col + 1];
            #pragma unroll
            for (int i = 0; i < 4; i++) {
                float2 v = unpack2(acc1[i][j]);
                float x0 = v.x * s0 + h0; x0 = (x0 >= 0.f) ? x0 : 0.1f * x0;
                float x1 = v.y * s1 + h1; x1 = (x1 >= 0.f) ? x1 : 0.1f * x1;
                *(float2*)(Hc + (rg * 4 + i) * HC_STRIDE + col) = make_float2(x0, x1);
            }
        }
        for (int i = tid; i < FDIM * FDIM; i += 256) {
            int f = i >> 7, kk = i & 127;
            Ws[kk * WS_STRIDE + f] = W2[f * HDIM + c * FDIM + kk];
        }
        __syncthreads();

        // GEMM2: E[64][128] += Hc @ W2c^T
        {
            const float* hb = Hc + (rg * 4) * HC_STRIDE;
            const float* wp = Ws + cg * 8;
            #pragma unroll 4
            for (int kk = 0; kk < FDIM; kk++) {
                float a0 = hb[0 * HC_STRIDE + kk];
                float a1 = hb[1 * HC_STRIDE + kk];
                float a2 = hb[2 * HC_STRIDE + kk];
                float a3 = hb[3 * HC_STRIDE + kk];
                ulonglong2 bq0 = *(const ulonglong2*)(wp + kk * WS_STRIDE);
                ulonglong2 bq1 = *(const ulonglong2*)(wp + kk * WS_STRIDE + 4);
                ull av0 = pack2(a0, a0), av1 = pack2(a1, a1);
                ull av2 = pack2(a2, a2), av3 = pack2(a3, a3);
                ull bv0 = bq0.x, bv1 = bq0.y, bv2 = bq1.x, bv3 = bq1.y;
                accE[0][0] = ffma2(av0, bv0, accE[0][0]); accE[0][1] = ffma2(av0, bv1, accE[0][1]);
                accE[0][2] = ffma2(av0, bv2, accE[0][2]); accE[0][3] = ffma2(av0, bv3, accE[0][3]);
                accE[1][0] = ffma2(av1, bv0, accE[1][0]); accE[1][1] = ffma2(av1, bv1, accE[1][1]);
                accE[1][2] = ffma2(av1, bv2, accE[1][2]); accE[1][3] = ffma2(av1, bv3, accE[1][3]);
                accE[2][0] = ffma2(av2, bv0, accE[2][0]); accE[2][1] = ffma2(av2, bv1, accE[2][1]);
                accE[2][2] = ffma2(av2, bv2, accE[2][2]); accE[2][3] = ffma2(av2, bv3, accE[2][3]);
                accE[3][0] = ffma2(av3, bv0, accE[3][0]); accE[3][1] = ffma2(av3, bv1, accE[3][1]);
                accE[3][2] = ffma2(av3, bv2, accE[3][2]); accE[3][3] = ffma2(av3, bv3, accE[3][3]);
            }
        }
    }

    // write E (+ b2) to scratch
    #pragma unroll
    for (int i = 0; i < 4; i++) {
        int r = r0 + rg * 4 + i;
        if (r < R3) {
            float* dst = g_E + (size_t)r * FDIM + cg * 8;
            #pragma unroll
            for (int j = 0; j < 4; j++) {
                float2 v = unpack2(accE[i][j]);
                v.x += b2[cg * 8 + 2 * j];
                v.y += b2[cg * 8 + 2 * j + 1];
                *(float2*)(dst + 2 * j) = v;
            }
        }
    }
}

// ===========================================================================
// Kernel B: one warp per sample -> d_pos2, d_neg2, triplet loss, key, L2 sum
// ===========================================================================
__global__ __launch_bounds__(256)
void dist_kernel(const int* __restrict__ user0, const int* __restrict__ posi, int N)
{
    int gw = (blockIdx.x * 256 + threadIdx.x) >> 5;
    int l = threadIdx.x & 31;
    float dp = 0.f, dn = 0.f, l2 = 0.f;
    if (gw < N) {
        float4 a = *((const float4*)g_E + (size_t)gw * 32 + l);
        float4 p = *((const float4*)g_E + (size_t)(N + gw) * 32 + l);
        float4 q = *((const float4*)g_E + (size_t)(2 * N + gw) * 32 + l);
        float d;
        d = a.x - p.x; dp += d * d; d = a.y - p.y; dp += d * d;
        d = a.z - p.z; dp += d * d; d = a.w - p.w; dp += d * d;
        d = a.x - q.x; dn += d * d; d = a.y - q.y; dn += d * d;
        d = a.z - q.z; dn += d * d; d = a.w - q.w; dn += d * d;
        l2 += a.x * a.x + a.y * a.y + a.z * a.z + a.w * a.w;
        l2 += p.x * p.x + p.y * p.y + p.z * p.z + p.w * p.w;
        l2 += q.x * q.x + q.y * q.y + q.z * q.z + q.w * q.w;
    }
    #pragma unroll
    for (int s = 16; s >= 1; s >>= 1) {
        dp += __shfl_xor_sync(0xffffffffu, dp, s);
        dn += __shfl_xor_sync(0xffffffffu, dn, s);
        l2 += __shfl_xor_sync(0xffffffffu, l2, s);
    }
    __shared__ float sl2[8];
    if (l == 0) {
        if (gw < N) {
            float lt = fmaxf(dp - dn + 0.5f, 0.f);
            g_lt[gw] = lt;
            g_key[gw] = ((ull)(unsigned)user0[gw] << 17) |
                        ((ull)(unsigned)posi[gw] << 1) |
                        (lt > 0.f ? 1ull : 0ull);
        }
        sl2[threadIdx.x >> 5] = l2;
    }
    __syncthreads();
    if (threadIdx.x == 0) {
        float s = 0.f;
        #pragma unroll
        for (int i = 0; i < 8; i++) s += sl2[i];
        atomicAdd(&g_l2sum, s);
    }
}

// ===========================================================================
// Kernel C: per-sample group count M (exact O(N^2) over keys in SMEM),
//           weight w = log(J*M/U + 1), accumulate sum(lt*w).
// Block: 64 samples x 4 scan-partitions = 256 threads.
// ===========================================================================
__global__ __launch_bounds__(256)
void weight_kernel(const float* __restrict__ dummy, const int* __restrict__ Jp,
                   const int* __restrict__ Up, int N)
{
    ull*   skey = (ull*)s_raw;               // [MAXN]
    int*   scnt = (int*)(skey + MAXN);       // [256]
    float* scon = (float*)(scnt + 256);      // [256]

    int t = threadIdx.x;
    for (int i = t; i < N; i += 256) skey[i] = g_key[i];
    __syncthreads();

    int li = t & 63, part = t >> 6;
    int i = blockIdx.x * 64 + li;
    ull myh = (i < N) ? (skey[i] >> 1) : ~0ull;
    int PART = (N + 3) >> 2;
    int j0 = part * PART, j1 = min(N, j0 + PART);
    int cnt = 0;
    #pragma unroll 4
    for (int j = j0; j < j1; j++) {
        ull kj = skey[j];
        cnt += (((kj >> 1) == myh) && (kj & 1ull)) ? 1 : 0;
    }
    scnt[t] = cnt;
    __syncthreads();

    float contrib = 0.f;
    if (part == 0 && i < N) {
        int M = scnt[li] + scnt[li + 64] + scnt[li + 128] + scnt[li + 192];
        int J = *Jp, U = *Up;
        float w = 0.f;
        if (U > 0) w = logf((float)J * (float)M / (float)U + 1.0f);
        contrib = g_lt[i] * w;
    }
    scon[t] = contrib;
    __syncthreads();
    if (t == 0) {
        float s = 0.f;
        for (int k = 0; k < 64; k++) s += scon[k];
        atomicAdd(&g_ltw, s);
    }
    (void)dummy;
}

// ===========================================================================
__global__ void zero_kernel() { g_l2sum = 0.f; g_ltw = 0.f; }

__global__ void finalize_kernel(float* out, int N)
{
    float ltm = g_ltw / (float)N;
    out[1] = ltm;
    out[0] = ltm + 1e-3f * g_l2sum / (float)N;
}

// ===========================================================================
extern "C" void kernel_launch(void* const* d_in, const int* in_sizes, int n_in,
                              void* d_out, int out_size)
{
    const int*   user0 = (const int*)d_in[0];
    const int*   posi  = (const int*)d_in[1];
    const int*   negi  = (const int*)d_in[2];
    // d_in[3] = ratings (unused by reference)
    const float* ut = (const float*)d_in[4];
    const float* it = (const float*)d_in[5];
    const float* W1 = (const float*)d_in[6];
    const float* b1 = (const float*)d_in[7];
    const float* ga = (const float*)d_in[8];
    const float* be = (const float*)d_in[9];
    const float* rm = (const float*)d_in[10];
    const float* rv = (const float*)d_in[11];
    const float* W2 = (const float*)d_in[12];
    const float* b2 = (const float*)d_in[13];
    const int*   Jp = (const int*)d_in[14];
    const int*   Up = (const int*)d_in[15];
    int N = in_sizes[0];
    if (N > MAXN) N = MAXN;

    const size_t smemA = (size_t)(FDIM * XS_STRIDE + FDIM * WS_STRIDE + 64 * HC_STRIDE
                                  + HDIM + HDIM + 64) * sizeof(float);
    const size_t smemC = (size_t)MAXN * sizeof(ull) + 512 * sizeof(int);
    cudaFuncSetAttribute(embed_filter_kernel, cudaFuncAttributeMaxDynamicSharedMemorySize, (int)smemA);
    cudaFuncSetAttribute(weight_kernel, cudaFuncAttributeMaxDynamicSharedMemorySize, (int)smemC);

    zero_kernel<<<1, 1>>>();
    int blocksA = (3 * N + 63) / 64;
    embed_filter_kernel<<<blocksA, 256, smemA>>>(user0, posi, negi, ut, it,
                                                 W1, b1, ga, be, rm, rv, W2, b2, N);
    dist_kernel<<<(N + 7) / 8, 256>>>(user0, posi, N);
    weight_kernel<<<(N + 63) / 64, 256, smemC>>>(nullptr, Jp, Up, N);
    finalize_kernel<<<1, 1>>>((float*)d_out, N);
}

// round 3
// speedup vs baseline: 3.3265x; 3.3265x over previous
#include <cuda_runtime.h>
#include <cuda_bf16.h>
#include <math.h>
#include <stdint.h>

#define MAXN   8192
#define FDIM   128
#define HDIM   512
#define TILE_M 128
#define HSLOTS 16384

#define SX 132   // fp32 tile row stride (elements): conflict-free fragment loads

typedef unsigned long long ull;

// ---------------- device scratch (no allocations allowed) ------------------
__device__ float g_E[3 * MAXN * FDIM];
__device__ float g_lt[MAXN];
__device__ int   g_slot[MAXN];
__device__ ull   g_hkey[HSLOTS];
__device__ int   g_hcnt[HSLOTS];
__device__ float g_l2sum;
__device__ float g_ltw;

// ---------------- helpers ---------------------------------------------------
__device__ __forceinline__ uint32_t f2tf32(float f) {
    uint32_t u;
    asm("cvt.rna.tf32.f32 %0, %1;" : "=r"(u) : "f"(f));
    return u;
}

__device__ __forceinline__ void mma_tf32(float c[4],
                                         uint32_t a0, uint32_t a1, uint32_t a2, uint32_t a3,
                                         uint32_t b0, uint32_t b1) {
    asm volatile("mma.sync.aligned.m16n8k8.row.col.f32.tf32.tf32.f32 "
                 "{%0,%1,%2,%3}, {%4,%5,%6,%7}, {%8,%9}, {%0,%1,%2,%3};"
                 : "+f"(c[0]), "+f"(c[1]), "+f"(c[2]), "+f"(c[3])
                 : "r"(a0), "r"(a1), "r"(a2), "r"(a3), "r"(b0), "r"(b1));
}

extern __shared__ float s_f[];

// stage a 128-row x 128-k fp32 chunk of W as tf32-rounded values, stride SX
__device__ __forceinline__ void stage_w(float* dst, const float* __restrict__ W,
                                        int rowbase, int ld, int kbase, int tid) {
    #pragma unroll
    for (int t = 0; t < 8; t++) {
        int idx = tid + t * 256;            // 0..2047
        int row = idx >> 4;
        int kq  = (idx & 15) * 8;
        const float4* p = (const float4*)(W + (size_t)(rowbase + row) * ld + kbase + kq);
        float4 a = p[0], b = p[1];
        uint4 o0 = make_uint4(f2tf32(a.x), f2tf32(a.y), f2tf32(a.z), f2tf32(a.w));
        uint4 o1 = make_uint4(f2tf32(b.x), f2tf32(b.y), f2tf32(b.z), f2tf32(b.w));
        *(uint4*)(dst + row * SX + kq)     = o0;
        *(uint4*)(dst + row * SX + kq + 4) = o1;
    }
}

// warp-tile GEMM: 32 rows x 64 cols per warp, K=128, m16n8k8 tf32 fragments
// A: row-major [.][SX] at warp's m base; B: row-major [n][SX] at warp's n base
__device__ __forceinline__ void gemm_tf32(float acc[2][8][4],
                                          const float* __restrict__ A,
                                          const float* __restrict__ B,
                                          int lr, int lq) {
    #pragma unroll 2
    for (int kt = 0; kt < 16; kt++) {
        const int k0 = kt * 8;
        uint32_t a[2][4];
        #pragma unroll
        for (int mt = 0; mt < 2; mt++) {
            const float* ap = A + (mt * 16 + lr) * SX + k0 + lq;
            a[mt][0] = __float_as_uint(ap[0]);
            a[mt][1] = __float_as_uint(ap[8 * SX]);
            a[mt][2] = __float_as_uint(ap[4]);
            a[mt][3] = __float_as_uint(ap[8 * SX + 4]);
        }
        #pragma unroll
        for (int nt = 0; nt < 8; nt++) {
            const float* bp = B + (nt * 8 + lr) * SX + k0 + lq;
            uint32_t b0 = __float_as_uint(bp[0]);
            uint32_t b1 = __float_as_uint(bp[4]);
            mma_tf32(acc[0][nt], a[0][0], a[0][1], a[0][2], a[0][3], b0, b1);
            mma_tf32(acc[1][nt], a[1][0], a[1][1], a[1][2], a[1][3], b0, b1);
        }
    }
}

// ===========================================================================
// Kernel A: gather + renorm + Linear/BN/LeakyReLU/Linear, 128 rows per CTA
// SMEM: X [128][SX] fp32, WA [128][SX], H [128][SX], bn float2[512]
// ===========================================================================
__global__ __launch_bounds__(256, 1)
void embed_mma_kernel(const int* __restrict__ user0, const int* __restrict__ posi,
                      const int* __restrict__ negi,
                      const float* __restrict__ ut, const float* __restrict__ it,
                      const float* __restrict__ W1, const float* __restrict__ b1,
                      const float* __restrict__ gamma1, const float* __restrict__ beta1,
                      const float* __restrict__ rmean, const float* __restrict__ rvar,
                      const float* __restrict__ W2, const float* __restrict__ b2, int N)
{
    const int tid  = threadIdx.x;
    const int wid  = tid >> 5;
    const int lane = tid & 31;
    const int lr   = lane >> 2;      // groupID 0..7
    const int lq   = lane & 3;       // threadID_in_group 0..3
    const int mg   = wid & 3;        // m group: rows mg*32
    const int nh   = wid >> 2;       // n half: cols nh*64

    float*  Xs = s_f;                        // 128*SX
    float*  Wa = Xs + TILE_M * SX;
    float*  Hs = Wa + TILE_M * SX;
    float2* bn = (float2*)(Hs + TILE_M * SX);
    float*  sE = Xs;                         // E staging reuses X region [128][130]

    const int R0 = blockIdx.x * TILE_M;

    // BN consts (fold b1)
    for (int h = tid; h < HDIM; h += 256) {
        float sc = gamma1[h] * rsqrtf(rvar[h] + 1e-5f);
        bn[h] = make_float2(sc, (b1[h] - rmean[h]) * sc + beta1[h]);
    }

    // X: gather + renorm + tf32 round (2 threads per row)
    {
        int row = tid >> 1, half = tid & 1;
        int R = R0 + row;
        const float* src = nullptr;
        if (R < 3 * N) {
            int g = R / N, n = R - g * N;
            int idx = (g == 0) ? user0[n] : (g == 1 ? posi[n] : negi[n]);
            src = ((g == 0) ? ut : it) + (size_t)idx * FDIM;
        }
        float4 v[16];
        float ss = 0.f;
        #pragma unroll
        for (int j = 0; j < 16; j++) {
            v[j] = src ? ((const float4*)src)[half * 16 + j] : make_float4(0.f, 0.f, 0.f, 0.f);
            ss += v[j].x * v[j].x + v[j].y * v[j].y + v[j].z * v[j].z + v[j].w * v[j].w;
        }
        ss += __shfl_xor_sync(0xffffffffu, ss, 1);
        float inv = 1.0f / fmaxf(sqrtf(ss), 1.0f);
        #pragma unroll
        for (int j = 0; j < 16; j++) {
            uint4 o = make_uint4(f2tf32(v[j].x * inv), f2tf32(v[j].y * inv),
                                 f2tf32(v[j].z * inv), f2tf32(v[j].w * inv));
            *(uint4*)(Xs + row * SX + half * 64 + j * 4) = o;
        }
    }
    __syncthreads();

    float accE[2][8][4];
    #pragma unroll
    for (int i = 0; i < 2; i++)
        #pragma unroll
        for (int j = 0; j < 8; j++)
            #pragma unroll
            for (int k = 0; k < 4; k++) accE[i][j][k] = 0.f;

    for (int c = 0; c < 4; c++) {
        stage_w(Wa, W1, c * FDIM, FDIM, 0, tid);
        __syncthreads();

        float acc1[2][8][4];
        #pragma unroll
        for (int i = 0; i < 2; i++)
            #pragma unroll
            for (int j = 0; j < 8; j++)
                #pragma unroll
                for (int k = 0; k < 4; k++) acc1[i][j][k] = 0.f;

        gemm_tf32(acc1, Xs + mg * 32 * SX, Wa + nh * 64 * SX, lr, lq);
        __syncthreads();                       // all GEMM1 reads of Wa done

        stage_w(Wa, W2, 0, HDIM, c * FDIM, tid);

        // BN + LeakyReLU -> Hs (tf32-rounded)
        #pragma unroll
        for (int mt = 0; mt < 2; mt++) {
            #pragma unroll
            for (int nt = 0; nt < 8; nt++) {
                int row = mg * 32 + mt * 16 + lr;
                int col = nh * 64 + nt * 8 + lq * 2;
                float2 p0 = bn[c * FDIM + col];
                float2 p1 = bn[c * FDIM + col + 1];
                float x0 = acc1[mt][nt][0] * p0.x + p0.y;
                float x1 = acc1[mt][nt][1] * p1.x + p1.y;
                float x2 = acc1[mt][nt][2] * p0.x + p0.y;
                float x3 = acc1[mt][nt][3] * p1.x + p1.y;
                x0 = (x0 >= 0.f) ? x0 : 0.1f * x0;
                x1 = (x1 >= 0.f) ? x1 : 0.1f * x1;
                x2 = (x2 >= 0.f) ? x2 : 0.1f * x2;
                x3 = (x3 >= 0.f) ? x3 : 0.1f * x3;
                *(uint32_t*)(Hs + row * SX + col)           = f2tf32(x0);
                *(uint32_t*)(Hs + row * SX + col + 1)       = f2tf32(x1);
                *(uint32_t*)(Hs + (row + 8) * SX + col)     = f2tf32(x2);
                *(uint32_t*)(Hs + (row + 8) * SX + col + 1) = f2tf32(x3);
            }
        }
        __syncthreads();

        gemm_tf32(accE, Hs + mg * 32 * SX, Wa + nh * 64 * SX, lr, lq);
        __syncthreads();                       // before Wa/Hs overwrite next iter
    }

    // E -> padded SMEM (float2, conflict-light) -> coalesced global write (+ b2)
    #pragma unroll
    for (int mt = 0; mt < 2; mt++) {
        #pragma unroll
        for (int nt = 0; nt < 8; nt++) {
            int row = mg * 32 + mt * 16 + lr;
            int col = nh * 64 + nt * 8 + lq * 2;
            *(float2*)(sE + row * 130 + col)       = make_float2(accE[mt][nt][0], accE[mt][nt][1]);
            *(float2*)(sE + (row + 8) * 130 + col) = make_float2(accE[mt][nt][2], accE[mt][nt][3]);
        }
    }
    __syncthreads();
    for (int i = tid; i < TILE_M * FDIM; i += 256) {
        int row = i >> 7, col = i & 127;
        int R = R0 + row;
        if (R < 3 * N) g_E[(size_t)R * FDIM + col] = sE[row * 130 + col] + b2[col];
    }
}

// ===========================================================================
// Kernel B: one warp per sample -> distances, triplet loss, L2 sum, hash insert
// ===========================================================================
__global__ __launch_bounds__(256)
void dist_hash_kernel(const int* __restrict__ user0, const int* __restrict__ posi, int N)
{
    int gw = (blockIdx.x * 256 + threadIdx.x) >> 5;
    int l = threadIdx.x & 31;
    float dp = 0.f, dn = 0.f, l2 = 0.f;
    if (gw < N) {
        float4 a = *((const float4*)g_E + (size_t)gw * 32 + l);
        float4 p = *((const float4*)g_E + (size_t)(N + gw) * 32 + l);
        float4 q = *((const float4*)g_E + (size_t)(2 * N + gw) * 32 + l);
        float d;
        d = a.x - p.x; dp += d * d; d = a.y - p.y; dp += d * d;
        d = a.z - p.z; dp += d * d; d = a.w - p.w; dp += d * d;
        d = a.x - q.x; dn += d * d; d = a.y - q.y; dn += d * d;
        d = a.z - q.z; dn += d * d; d = a.w - q.w; dn += d * d;
        l2 += a.x * a.x + a.y * a.y + a.z * a.z + a.w * a.w;
        l2 += p.x * p.x + p.y * p.y + p.z * p.z + p.w * p.w;
        l2 += q.x * q.x + q.y * q.y + q.z * q.z + q.w * q.w;
    }
    #pragma unroll
    for (int s = 16; s >= 1; s >>= 1) {
        dp += __shfl_xor_sync(0xffffffffu, dp, s);
        dn += __shfl_xor_sync(0xffffffffu, dn, s);
        l2 += __shfl_xor_sync(0xffffffffu, l2, s);
    }
    __shared__ float sl2[8];
    if (l == 0) {
        if (gw < N) {
            float lt = fmaxf(dp - dn + 0.5f, 0.f);
            g_lt[gw] = lt;
            ull key = ((ull)(unsigned)user0[gw] << 17) | ((ull)(unsigned)posi[gw]);
            uint32_t slot = (uint32_t)((key * 0x9E3779B97F4A7C15ull) >> 50);
            for (;;) {
                ull old = atomicCAS(&g_hkey[slot], ~0ull, key);
                if (old == ~0ull || old == key) {
                    if (lt > 0.f) atomicAdd(&g_hcnt[slot], 1);
                    g_slot[gw] = (int)slot;
                    break;
                }
                slot = (slot + 1) & (HSLOTS - 1);
            }
        }
        sl2[threadIdx.x >> 5] = l2;
    }
    __syncthreads();
    if (threadIdx.x == 0) {
        float s = 0.f;
        #pragma unroll
        for (int i = 0; i < 8; i++) s += sl2[i];
        atomicAdd(&g_l2sum, s);
    }
}

// ===========================================================================
__global__ __launch_bounds__(256)
void weight_kernel(const int* __restrict__ Jp, const int* __restrict__ Up, int N)
{
    int i = blockIdx.x * 256 + threadIdx.x;
    float contrib = 0.f;
    if (i < N) {
        int M = g_hcnt[g_slot[i]];
        int J = *Jp, U = *Up;
        float w = (U > 0) ? logf((float)J * (float)M / (float)U + 1.0f) : 0.0f;
        contrib = g_lt[i] * w;
    }
    #pragma unroll
    for (int s = 16; s >= 1; s >>= 1)
        contrib += __shfl_xor_sync(0xffffffffu, contrib, s);
    __shared__ float sw[8];
    if ((threadIdx.x & 31) == 0) sw[threadIdx.x >> 5] = contrib;
    __syncthreads();
    if (threadIdx.x == 0) {
        float s = 0.f;
        #pragma unroll
        for (int k = 0; k < 8; k++) s += sw[k];
        atomicAdd(&g_ltw, s);
    }
}

__global__ void zero_kernel()
{
    int i = blockIdx.x * 256 + threadIdx.x;
    if (i < HSLOTS) { g_hkey[i] = ~0ull; g_hcnt[i] = 0; }
    if (i == 0) { g_l2sum = 0.f; g_ltw = 0.f; }
}

__global__ void finalize_kernel(float* out, int N)
{
    float ltm = g_ltw / (float)N;
    out[1] = ltm;
    out[0] = ltm + 1e-3f * g_l2sum / (float)N;
}

// ===========================================================================
extern "C" void kernel_launch(void* const* d_in, const int* in_sizes, int n_in,
                              void* d_out, int out_size)
{
    const int*   user0 = (const int*)d_in[0];
    const int*   posi  = (const int*)d_in[1];
    const int*   negi  = (const int*)d_in[2];
    // d_in[3] = ratings (unused)
    const float* ut = (const float*)d_in[4];
    const float* it = (const float*)d_in[5];
    const float* W1 = (const float*)d_in[6];
    const float* b1 = (const float*)d_in[7];
    const float* ga = (const float*)d_in[8];
    const float* be = (const float*)d_in[9];
    const float* rm = (const float*)d_in[10];
    const float* rv = (const float*)d_in[11];
    const float* W2 = (const float*)d_in[12];
    const float* b2 = (const float*)d_in[13];
    const int*   Jp = (const int*)d_in[14];
    const int*   Up = (const int*)d_in[15];
    int N = in_sizes[0];
    if (N > MAXN) N = MAXN;

    // SMEM: 3 tiles of 128*SX floats + bn 4KB
    const int smemA = (3 * TILE_M * SX + 2 * HDIM) * (int)sizeof(float);   // 206848
    cudaFuncSetAttribute(embed_mma_kernel, cudaFuncAttributeMaxDynamicSharedMemorySize, smemA);

    zero_kernel<<<(HSLOTS + 255) / 256, 256>>>();
    int blocksA = (3 * N + TILE_M - 1) / TILE_M;
    embed_mma_kernel<<<blocksA, 256, smemA>>>(user0, posi, negi, ut, it,
                                              W1, b1, ga, be, rm, rv, W2, b2, N);
    dist_hash_kernel<<<(N + 7) / 8, 256>>>(user0, posi, N);
    weight_kernel<<<(N + 255) / 256, 256>>>(Jp, Up, N);
    finalize_kernel<<<1, 1>>>((float*)d_out, N);
}

// round 5
// speedup vs baseline: 4.4522x; 1.3384x over previous
#include <cuda_runtime.h>
#include <cuda_bf16.h>
#include <math.h>
#include <stdint.h>

#define MAXN   8192
#define FDIM   128
#define HDIM   512
#define TILE_M 128
#define HSLOTS 16384

#define SXB 136   // bf16 tile row stride (elements); 272B -> ldmatrix conflict-free

typedef unsigned long long ull;

// ---------------- device scratch (no allocations allowed) ------------------
__device__ float g_E[3 * MAXN * FDIM];
__device__ float g_lt[MAXN];
__device__ int   g_slot[MAXN];
__device__ ull   g_hkey[HSLOTS];
__device__ int   g_hcnt[HSLOTS];
__device__ float g_l2sum;
__device__ float g_ltw;
__device__ int   g_done;

// ---------------- helpers ---------------------------------------------------
__device__ __forceinline__ uint32_t smem_u32(const void* p) {
    uint32_t a;
    asm("{ .reg .u64 t; cvta.to.shared.u64 t, %1; cvt.u32.u64 %0, t; }" : "=r"(a) : "l"(p));
    return a;
}

#define LDSM4(r0, r1, r2, r3, a) \
    asm volatile("ldmatrix.sync.aligned.m8n8.x4.shared.b16 {%0,%1,%2,%3}, [%4];" \
        : "=r"(r0), "=r"(r1), "=r"(r2), "=r"(r3) : "r"(a))

__device__ __forceinline__ void mma_bf16(float c[4],
                                         uint32_t a0, uint32_t a1, uint32_t a2, uint32_t a3,
                                         uint32_t b0, uint32_t b1) {
    asm volatile("mma.sync.aligned.m16n8k16.row.col.f32.bf16.bf16.f32 "
                 "{%0,%1,%2,%3}, {%4,%5,%6,%7}, {%8,%9}, {%0,%1,%2,%3};"
                 : "+f"(c[0]), "+f"(c[1]), "+f"(c[2]), "+f"(c[3])
                 : "r"(a0), "r"(a1), "r"(a2), "r"(a3), "r"(b0), "r"(b1));
}

__device__ __forceinline__ uint32_t pack_bf2(float x, float y) {
    __nv_bfloat162 b = __floats2bfloat162_rn(x, y);
    return *(uint32_t*)&b;
}

extern __shared__ __nv_bfloat16 s_b[];

// stage a 128-row x 128-k fp32 chunk of W as bf16 into padded tile
__device__ __forceinline__ void stage_wb(__nv_bfloat16* dst, const float* __restrict__ W,
                                         int rowbase, int ld, int kbase, int tid) {
    #pragma unroll
    for (int t = 0; t < 8; t++) {
        int idx = tid + t * 256;            // 0..2047
        int row = idx >> 4;
        int kq  = (idx & 15) * 8;
        const float4* p = (const float4*)(W + (size_t)(rowbase + row) * ld + kbase + kq);
        float4 a = p[0], b = p[1];
        uint4 o = make_uint4(pack_bf2(a.x, a.y), pack_bf2(a.z, a.w),
                             pack_bf2(b.x, b.y), pack_bf2(b.z, b.w));
        *(uint4*)(dst + row * SXB + kq) = o;
    }
}

// warp-tile GEMM: 32 rows x 64 cols per warp, K=128, bf16 m16n8k16 via ldmatrix
// Aaddr0/Baddr0 = tile base smem addr + per-thread ldmatrix offset (k=0)
__device__ __forceinline__ void gemm_bf16_tile(float acc[2][8][4],
                                               uint32_t Aaddr0, uint32_t Baddr0) {
    #pragma unroll
    for (int kt = 0; kt < 8; kt++) {
        const uint32_t ko = kt * 32;       // 16 bf16 = 32 bytes per k-step
        uint32_t a0, a1, a2, a3, a4, a5, a6, a7;
        LDSM4(a0, a1, a2, a3, Aaddr0 + ko);
        LDSM4(a4, a5, a6, a7, Aaddr0 + 16 * SXB * 2 + ko);
        uint32_t b[8][2];
        #pragma unroll
        for (int p = 0; p < 4; p++)
            LDSM4(b[2 * p][0], b[2 * p][1], b[2 * p + 1][0], b[2 * p + 1][1],
                  Baddr0 + (uint32_t)p * (16 * SXB * 2) + ko);
        #pragma unroll
        for (int nt = 0; nt < 8; nt++) {
            mma_bf16(acc[0][nt], a0, a1, a2, a3, b[nt][0], b[nt][1]);
            mma_bf16(acc[1][nt], a4, a5, a6, a7, b[nt][0], b[nt][1]);
        }
    }
}

// ===========================================================================
// Kernel A: gather + renorm + Linear/BN/LeakyReLU/Linear, 128 rows per CTA
// SMEM: Xs/Wa/Hs bf16 [128][SXB] (34816B each), bn float2[512]
// Also clears the hash table (blocks 0..63) and global accumulators.
// ===========================================================================
__global__ __launch_bounds__(256, 1)
void embed_bf16_kernel(const int* __restrict__ user0, const int* __restrict__ posi,
                       const int* __restrict__ negi,
                       const float* __restrict__ ut, const float* __restrict__ it,
                       const float* __restrict__ W1, const float* __restrict__ b1,
                       const float* __restrict__ gamma1, const float* __restrict__ beta1,
                       const float* __restrict__ rmean, const float* __restrict__ rvar,
                       const float* __restrict__ W2, const float* __restrict__ b2, int N)
{
    const int tid  = threadIdx.x;
    const int wid  = tid >> 5;
    const int lane = tid & 31;
    const int lr   = lane >> 2;      // C-frag row within 16
    const int lq   = lane & 3;       // C-frag col pair
    const int mg   = wid & 3;        // m group: rows mg*32
    const int nh   = wid >> 2;       // n half: cols nh*64

    __nv_bfloat16* Xs = s_b;
    __nv_bfloat16* Wa = Xs + TILE_M * SXB;
    __nv_bfloat16* Hs = Wa + TILE_M * SXB;
    float2*        bn = (float2*)(Hs + TILE_M * SXB);
    float*         sE = (float*)s_b;          // output staging reuses Xs+Wa

    const int R0 = blockIdx.x * TILE_M;

    // clear hash table + accumulators (runs before dist kernel by stream order)
    if (blockIdx.x < HSLOTS / 256) {
        int i = blockIdx.x * 256 + tid;
        g_hkey[i] = ~0ull;
        g_hcnt[i] = 0;
        if (i == 0) { g_l2sum = 0.f; g_ltw = 0.f; g_done = 0; }
    }

    // BN consts (fold b1)
    for (int h = tid; h < HDIM; h += 256) {
        float sc = gamma1[h] * rsqrtf(rvar[h] + 1e-5f);
        bn[h] = make_float2(sc, (b1[h] - rmean[h]) * sc + beta1[h]);
    }

    // X: gather + renorm + bf16 (2 threads per row)
    {
        int row = tid >> 1, half = tid & 1;
        int R = R0 + row;
        const float* src = nullptr;
        if (R < 3 * N) {
            int g = R / N, n = R - g * N;
            int idx = (g == 0) ? user0[n] : (g == 1 ? posi[n] : negi[n]);
            src = ((g == 0) ? ut : it) + (size_t)idx * FDIM;
        }
        float4 v[16];
        float ss = 0.f;
        #pragma unroll
        for (int j = 0; j < 16; j++) {
            v[j] = src ? ((const float4*)src)[half * 16 + j] : make_float4(0.f, 0.f, 0.f, 0.f);
            ss += v[j].x * v[j].x + v[j].y * v[j].y + v[j].z * v[j].z + v[j].w * v[j].w;
        }
        ss += __shfl_xor_sync(0xffffffffu, ss, 1);
        float inv = 1.0f / fmaxf(sqrtf(ss), 1.0f);
        #pragma unroll
        for (int j = 0; j < 16; j += 2) {
            uint4 o = make_uint4(pack_bf2(v[j].x * inv, v[j].y * inv),
                                 pack_bf2(v[j].z * inv, v[j].w * inv),
                                 pack_bf2(v[j+1].x * inv, v[j+1].y * inv),
                                 pack_bf2(v[j+1].z * inv, v[j+1].w * inv));
            *(uint4*)(Xs + row * SXB + half * 64 + j * 4) = o;
        }
    }
    __syncthreads();

    // per-thread ldmatrix offsets (bytes)
    const int lg = lane >> 3, lw = lane & 7;
    const uint32_t xb = smem_u32(Xs), wb = smem_u32(Wa), hb = smem_u32(Hs);
    const uint32_t aoff = (uint32_t)(((mg * 32 + (lg & 1) * 8 + lw) * SXB + (lg >> 1) * 8) * 2);
    const uint32_t boff = (uint32_t)(((nh * 64 + (lg >> 1) * 8 + lw) * SXB + (lg & 1) * 8) * 2);

    float accE[2][8][4];
    #pragma unroll
    for (int i = 0; i < 2; i++)
        #pragma unroll
        for (int j = 0; j < 8; j++)
            #pragma unroll
            for (int k = 0; k < 4; k++) accE[i][j][k] = 0.f;

    for (int c = 0; c < 4; c++) {
        stage_wb(Wa, W1, c * FDIM, FDIM, 0, tid);
        __syncthreads();

        float acc1[2][8][4];
        #pragma unroll
        for (int i = 0; i < 2; i++)
            #pragma unroll
            for (int j = 0; j < 8; j++)
                #pragma unroll
                for (int k = 0; k < 4; k++) acc1[i][j][k] = 0.f;

        gemm_bf16_tile(acc1, xb + aoff, wb + boff);
        __syncthreads();                  // GEMM1 reads of Wa complete

        stage_wb(Wa, W2, 0, HDIM, c * FDIM, tid);

        // BN + LeakyReLU -> Hs (bf16)
        #pragma unroll
        for (int mt = 0; mt < 2; mt++) {
            #pragma unroll
            for (int nt = 0; nt < 8; nt++) {
                int row = mg * 32 + mt * 16 + lr;
                int col = nh * 64 + nt * 8 + lq * 2;
                float2 p0 = bn[c * FDIM + col];
                float2 p1 = bn[c * FDIM + col + 1];
                float x0 = acc1[mt][nt][0] * p0.x + p0.y;
                float x1 = acc1[mt][nt][1] * p1.x + p1.y;
                float x2 = acc1[mt][nt][2] * p0.x + p0.y;
                float x3 = acc1[mt][nt][3] * p1.x + p1.y;
                x0 = (x0 >= 0.f) ? x0 : 0.1f * x0;
                x1 = (x1 >= 0.f) ? x1 : 0.1f * x1;
                x2 = (x2 >= 0.f) ? x2 : 0.1f * x2;
                x3 = (x3 >= 0.f) ? x3 : 0.1f * x3;
                *(uint32_t*)(Hs + row * SXB + col)       = pack_bf2(x0, x1);
                *(uint32_t*)(Hs + (row + 8) * SXB + col) = pack_bf2(x2, x3);
            }
        }
        __syncthreads();

        gemm_bf16_tile(accE, hb + aoff, wb + boff);
        __syncthreads();                  // before Wa/Hs overwrite (or sE write)
    }

    // E -> padded SMEM -> coalesced global write (+ b2)
    #pragma unroll
    for (int mt = 0; mt < 2; mt++) {
        #pragma unroll
        for (int nt = 0; nt < 8; nt++) {
            int row = mg * 32 + mt * 16 + lr;
            int col = nh * 64 + nt * 8 + lq * 2;
            *(float2*)(sE + row * 130 + col)       = make_float2(accE[mt][nt][0], accE[mt][nt][1]);
            *(float2*)(sE + (row + 8) * 130 + col) = make_float2(accE[mt][nt][2], accE[mt][nt][3]);
        }
    }
    __syncthreads();
    for (int i = tid; i < TILE_M * FDIM; i += 256) {
        int row = i >> 7, col = i & 127;
        int R = R0 + row;
        if (R < 3 * N) g_E[(size_t)R * FDIM + col] = sE[row * 130 + col] + b2[col];
    }
}

// ===========================================================================
// Kernel B: one warp per sample -> distances, triplet loss, L2 sum, hash insert
// ===========================================================================
__global__ __launch_bounds__(256)
void dist_hash_kernel(const int* __restrict__ user0, const int* __restrict__ posi, int N)
{
    int gw = (blockIdx.x * 256 + threadIdx.x) >> 5;
    int l = threadIdx.x & 31;
    float dp = 0.f, dn = 0.f, l2 = 0.f;
    if (gw < N) {
        float4 a = *((const float4*)g_E + (size_t)gw * 32 + l);
        float4 p = *((const float4*)g_E + (size_t)(N + gw) * 32 + l);
        float4 q = *((const float4*)g_E + (size_t)(2 * N + gw) * 32 + l);
        float d;
        d = a.x - p.x; dp += d * d; d = a.y - p.y; dp += d * d;
        d = a.z - p.z; dp += d * d; d = a.w - p.w; dp += d * d;
        d = a.x - q.x; dn += d * d; d = a.y - q.y; dn += d * d;
        d = a.z - q.z; dn += d * d; d = a.w - q.w; dn += d * d;
        l2 += a.x * a.x + a.y * a.y + a.z * a.z + a.w * a.w;
        l2 += p.x * p.x + p.y * p.y + p.z * p.z + p.w * p.w;
        l2 += q.x * q.x + q.y * q.y + q.z * q.z + q.w * q.w;
    }
    #pragma unroll
    for (int s = 16; s >= 1; s >>= 1) {
        dp += __shfl_xor_sync(0xffffffffu, dp, s);
        dn += __shfl_xor_sync(0xffffffffu, dn, s);
        l2 += __shfl_xor_sync(0xffffffffu, l2, s);
    }
    __shared__ float sl2[8];
    if (l == 0) {
        if (gw < N) {
            float lt = fmaxf(dp - dn + 0.5f, 0.f);
            g_lt[gw] = lt;
            ull key = ((ull)(unsigned)user0[gw] << 17) | ((ull)(unsigned)posi[gw]);
            uint32_t slot = (uint32_t)((key * 0x9E3779B97F4A7C15ull) >> 50);
            for (;;) {
                ull old = atomicCAS(&g_hkey[slot], ~0ull, key);
                if (old == ~0ull || old == key) {
                    if (lt > 0.f) atomicAdd(&g_hcnt[slot], 1);
                    g_slot[gw] = (int)slot;
                    break;
                }
                slot = (slot + 1) & (HSLOTS - 1);
            }
        }
        sl2[threadIdx.x >> 5] = l2;
    }
    __syncthreads();
    if (threadIdx.x == 0) {
        float s = 0.f;
        #pragma unroll
        for (int i = 0; i < 8; i++) s += sl2[i];
        atomicAdd(&g_l2sum, s);
    }
}

// ===========================================================================
// Kernel C: weight lookup + weighted loss reduction + last-block finalize
// ===========================================================================
__global__ __launch_bounds__(256)
void weight_finalize_kernel(const int* __restrict__ Jp, const int* __restrict__ Up,
                            int N, float* __restrict__ out)
{
    int i = blockIdx.x * 256 + threadIdx.x;
    float contrib = 0.f;
    if (i < N) {
        int M = g_hcnt[g_slot[i]];
        int J = *Jp, U = *Up;
        float w = (U > 0) ? logf((float)J * (float)M / (float)U + 1.0f) : 0.0f;
        contrib = g_lt[i] * w;
    }
    #pragma unroll
    for (int s = 16; s >= 1; s >>= 1)
        contrib += __shfl_xor_sync(0xffffffffu, contrib, s);
    __shared__ float sw[8];
    if ((threadIdx.x & 31) == 0) sw[threadIdx.x >> 5] = contrib;
    __syncthreads();
    if (threadIdx.x == 0) {
        float s = 0.f;
        #pragma unroll
        for (int k = 0; k < 8; k++) s += sw[k];
        atomicAdd(&g_ltw, s);
        __threadfence();
        int prev = atomicAdd(&g_done, 1);
        if (prev == (int)gridDim.x - 1) {
            float ltw = atomicAdd(&g_ltw, 0.f);
            float l2  = atomicAdd(&g_l2sum, 0.f);
            float ltm = ltw / (float)N;
            out[1] = ltm;
            out[0] = ltm + 1e-3f * l2 / (float)N;
            g_done = 0;
        }
    }
}

// ===========================================================================
extern "C" void kernel_launch(void* const* d_in, const int* in_sizes, int n_in,
                              void* d_out, int out_size)
{
    const int*   user0 = (const int*)d_in[0];
    const int*   posi  = (const int*)d_in[1];
    const int*   negi  = (const int*)d_in[2];
    // d_in[3] = ratings (unused)
    const float* ut = (const float*)d_in[4];
    const float* it = (const float*)d_in[5];
    const float* W1 = (const float*)d_in[6];
    const float* b1 = (const float*)d_in[7];
    const float* ga = (const float*)d_in[8];
    const float* be = (const float*)d_in[9];
    const float* rm = (const float*)d_in[10];
    const float* rv = (const float*)d_in[11];
    const float* W2 = (const float*)d_in[12];
    const float* b2 = (const float*)d_in[13];
    const int*   Jp = (const int*)d_in[14];
    const int*   Up = (const int*)d_in[15];
    int N = in_sizes[0];
    if (N > MAXN) N = MAXN;

    // SMEM: 3 bf16 tiles [128][SXB] + bn float2[512]
    const int smemA = 3 * TILE_M * SXB * 2 + HDIM * 8;   // 108544
    cudaFuncSetAttribute(embed_bf16_kernel, cudaFuncAttributeMaxDynamicSharedMemorySize, smemA);

    int blocksA = (3 * N + TILE_M - 1) / TILE_M;
    embed_bf16_kernel<<<blocksA, 256, smemA>>>(user0, posi, negi, ut, it,
                                               W1, b1, ga, be, rm, rv, W2, b2, N);
    dist_hash_kernel<<<(N + 7) / 8, 256>>>(user0, posi, N);
    weight_finalize_kernel<<<(N + 255) / 256, 256>>>(Jp, Up, N, (float*)d_out);
}

// round 7
// speedup vs baseline: 4.7869x; 1.0752x over previous
#include <cuda_runtime.h>
#include <cuda_bf16.h>
#include <math.h>
#include <stdint.h>

#define MAXN   8192
#define FDIM   128
#define HDIM   512
#define TILE_M 64
#define HSLOTS 16384

#define SXB 136   // bf16 tile row stride (elements); 272B -> ldmatrix conflict-free

typedef unsigned long long ull;

// ---------------- device scratch (no allocations allowed) ------------------
__device__ float g_E[3 * MAXN * FDIM];
__device__ float g_lt[MAXN];
__device__ int   g_slot[MAXN];
__device__ ull   g_hkey[HSLOTS];
__device__ int   g_hcnt[HSLOTS];
__device__ float g_l2sum;
__device__ float g_ltw;
__device__ int   g_done;

// ---------------- helpers ---------------------------------------------------
__device__ __forceinline__ uint32_t smem_u32(const void* p) {
    uint32_t a;
    asm("{ .reg .u64 t; cvta.to.shared.u64 t, %1; cvt.u32.u64 %0, t; }" : "=r"(a) : "l"(p));
    return a;
}

#define LDSM4(r0, r1, r2, r3, a) \
    asm volatile("ldmatrix.sync.aligned.m8n8.x4.shared.b16 {%0,%1,%2,%3}, [%4];" \
        : "=r"(r0), "=r"(r1), "=r"(r2), "=r"(r3) : "r"(a))

__device__ __forceinline__ void mma_bf16(float c[4],
                                         uint32_t a0, uint32_t a1, uint32_t a2, uint32_t a3,
                                         uint32_t b0, uint32_t b1) {
    asm volatile("mma.sync.aligned.m16n8k16.row.col.f32.bf16.bf16.f32 "
                 "{%0,%1,%2,%3}, {%4,%5,%6,%7}, {%8,%9}, {%0,%1,%2,%3};"
                 : "+f"(c[0]), "+f"(c[1]), "+f"(c[2]), "+f"(c[3])
                 : "r"(a0), "r"(a1), "r"(a2), "r"(a3), "r"(b0), "r"(b1));
}

__device__ __forceinline__ uint32_t pack_bf2(float x, float y) {
    __nv_bfloat162 b = __floats2bfloat162_rn(x, y);
    return *(uint32_t*)&b;
}

extern __shared__ __nv_bfloat16 s_b[];

// stage a 128-row x 128-k fp32 chunk of W as bf16 into padded tile
__device__ __forceinline__ void stage_wb(__nv_bfloat16* dst, const float* __restrict__ W,
                                         int rowbase, int ld, int kbase, int tid) {
    #pragma unroll
    for (int t = 0; t < 8; t++) {
        int idx = tid + t * 256;            // 0..2047
        int row = idx >> 4;
        int kq  = (idx & 15) * 8;
        const float4* p = (const float4*)(W + (size_t)(rowbase + row) * ld + kbase + kq);
        float4 a = p[0], b = p[1];
        uint4 o = make_uint4(pack_bf2(a.x, a.y), pack_bf2(a.z, a.w),
                             pack_bf2(b.x, b.y), pack_bf2(b.z, b.w));
        *(uint4*)(dst + row * SXB + kq) = o;
    }
}

// warp-tile GEMM: 16 rows x 64 cols per warp, K=128, bf16 m16n8k16 via ldmatrix
__device__ __forceinline__ void gemm_bf16_tile(float acc[8][4],
                                               uint32_t Aaddr0, uint32_t Baddr0) {
    #pragma unroll
    for (int kt = 0; kt < 8; kt++) {
        const uint32_t ko = kt * 32;       // 16 bf16 = 32 bytes per k-step
        uint32_t a0, a1, a2, a3;
        LDSM4(a0, a1, a2, a3, Aaddr0 + ko);
        uint32_t b[8][2];
        #pragma unroll
        for (int p = 0; p < 4; p++)
            LDSM4(b[2 * p][0], b[2 * p][1], b[2 * p + 1][0], b[2 * p + 1][1],
                  Baddr0 + (uint32_t)p * (16 * SXB * 2) + ko);
        #pragma unroll
        for (int nt = 0; nt < 8; nt++)
            mma_bf16(acc[nt], a0, a1, a2, a3, b[nt][0], b[nt][1]);
    }
}

// ===========================================================================
// Kernel A: gather + renorm + Linear/BN/LeakyReLU/Linear, 64 rows per CTA
// 2 CTAs/SM (regs capped at 128): co-resident CTA hides staging/barrier stalls.
// SMEM: Xs/Hs bf16 [64][SXB], Wa bf16 [128][SXB], bn float2[512]  = 72KB
// ===========================================================================
__global__ __launch_bounds__(256, 2)
void embed_bf16_kernel(const int* __restrict__ user0, const int* __restrict__ posi,
                       const int* __restrict__ negi,
                       const float* __restrict__ ut, const float* __restrict__ it,
                       const float* __restrict__ W1, const float* __restrict__ b1,
                       const float* __restrict__ gamma1, const float* __restrict__ beta1,
                       const float* __restrict__ rmean, const float* __restrict__ rvar,
                       const float* __restrict__ W2, const float* __restrict__ b2, int N)
{
    const int tid  = threadIdx.x;
    const int wid  = tid >> 5;
    const int lane = tid & 31;
    const int lr   = lane >> 2;      // C-frag row within 16
    const int lq   = lane & 3;       // C-frag col pair
    const int mg   = wid & 3;        // m group: rows mg*16
    const int nh   = wid >> 2;       // n half: cols nh*64

    __nv_bfloat16* Xs = s_b;                       // 64*SXB
    __nv_bfloat16* Hs = Xs + TILE_M * SXB;         // 64*SXB
    __nv_bfloat16* Wa = Hs + TILE_M * SXB;         // 128*SXB
    float2*        bn = (float2*)(Wa + FDIM * SXB);
    float*         sE = (float*)s_b;               // out staging reuses Xs+Hs (33.3KB)

    const int R0 = blockIdx.x * TILE_M;

    // clear hash table + accumulators (runs before dist kernel by stream order)
    if (blockIdx.x < HSLOTS / 256) {
        int i = blockIdx.x * 256 + tid;
        g_hkey[i] = ~0ull;
        g_hcnt[i] = 0;
        if (i == 0) { g_l2sum = 0.f; g_ltw = 0.f; g_done = 0; }
    }

    // BN consts (fold b1)
    for (int h = tid; h < HDIM; h += 256) {
        float sc = gamma1[h] * rsqrtf(rvar[h] + 1e-5f);
        bn[h] = make_float2(sc, (b1[h] - rmean[h]) * sc + beta1[h]);
    }

    // X: gather + renorm + bf16 (4 threads per row, 32 cols each)
    {
        int row = tid >> 2;
        int q   = tid & 3;
        int R = R0 + row;
        const float* src = nullptr;
        if (R < 3 * N) {
            int g = R / N, n = R - g * N;
            int idx = (g == 0) ? user0[n] : (g == 1 ? posi[n] : negi[n]);
            src = ((g == 0) ? ut : it) + (size_t)idx * FDIM;
        }
        float4 v[8];
        float ss = 0.f;
        #pragma unroll
        for (int j = 0; j < 8; j++) {
            v[j] = src ? ((const float4*)src)[q * 8 + j] : make_float4(0.f, 0.f, 0.f, 0.f);
            ss += v[j].x * v[j].x + v[j].y * v[j].y + v[j].z * v[j].z + v[j].w * v[j].w;
        }
        ss += __shfl_xor_sync(0xffffffffu, ss, 1);
        ss += __shfl_xor_sync(0xffffffffu, ss, 2);
        float inv = 1.0f / fmaxf(sqrtf(ss), 1.0f);
        #pragma unroll
        for (int j = 0; j < 8; j += 2) {
            uint4 o = make_uint4(pack_bf2(v[j].x * inv, v[j].y * inv),
                                 pack_bf2(v[j].z * inv, v[j].w * inv),
                                 pack_bf2(v[j+1].x * inv, v[j+1].y * inv),
                                 pack_bf2(v[j+1].z * inv, v[j+1].w * inv));
            *(uint4*)(Xs + row * SXB + q * 32 + j * 4) = o;
        }
    }
    __syncthreads();

    // per-thread ldmatrix offsets (bytes)
    const int lg = lane >> 3, lw = lane & 7;
    const uint32_t xb = smem_u32(Xs), wb = smem_u32(Wa), hb = smem_u32(Hs);
    const uint32_t aoff = (uint32_t)(((mg * 16 + (lg & 1) * 8 + lw) * SXB + (lg >> 1) * 8) * 2);
    const uint32_t boff = (uint32_t)(((nh * 64 + (lg >> 1) * 8 + lw) * SXB + (lg & 1) * 8) * 2);

    float accE[8][4];
    #pragma unroll
    for (int j = 0; j < 8; j++)
        #pragma unroll
        for (int k = 0; k < 4; k++) accE[j][k] = 0.f;

    for (int c = 0; c < 4; c++) {
        stage_wb(Wa, W1, c * FDIM, FDIM, 0, tid);
        __syncthreads();

        float acc1[8][4];
        #pragma unroll
        for (int j = 0; j < 8; j++)
            #pragma unroll
            for (int k = 0; k < 4; k++) acc1[j][k] = 0.f;

        gemm_bf16_tile(acc1, xb + aoff, wb + boff);
        __syncthreads();                  // GEMM1 reads of Wa complete

        stage_wb(Wa, W2, 0, HDIM, c * FDIM, tid);

        // BN + LeakyReLU -> Hs (bf16)
        #pragma unroll
        for (int nt = 0; nt < 8; nt++) {
            int row = mg * 16 + lr;
            int col = nh * 64 + nt * 8 + lq * 2;
            float2 p0 = bn[c * FDIM + col];
            float2 p1 = bn[c * FDIM + col + 1];
            float x0 = acc1[nt][0] * p0.x + p0.y;
            float x1 = acc1[nt][1] * p1.x + p1.y;
            float x2 = acc1[nt][2] * p0.x + p0.y;
            float x3 = acc1[nt][3] * p1.x + p1.y;
            x0 = (x0 >= 0.f) ? x0 : 0.1f * x0;
            x1 = (x1 >= 0.f) ? x1 : 0.1f * x1;
            x2 = (x2 >= 0.f) ? x2 : 0.1f * x2;
            x3 = (x3 >= 0.f) ? x3 : 0.1f * x3;
            *(uint32_t*)(Hs + row * SXB + col)       = pack_bf2(x0, x1);
            *(uint32_t*)(Hs + (row + 8) * SXB + col) = pack_bf2(x2, x3);
        }
        __syncthreads();

        gemm_bf16_tile(accE, hb + aoff, wb + boff);
        __syncthreads();                  // before Wa/Hs overwrite (or sE write)
    }

    // E -> padded SMEM -> coalesced global write (+ b2)
    #pragma unroll
    for (int nt = 0; nt < 8; nt++) {
        int row = mg * 16 + lr;
        int col = nh * 64 + nt * 8 + lq * 2;
        *(float2*)(sE + row * 130 + col)       = make_float2(accE[nt][0], accE[nt][1]);
        *(float2*)(sE + (row + 8) * 130 + col) = make_float2(accE[nt][2], accE[nt][3]);
    }
    __syncthreads();
    for (int i = tid; i < TILE_M * FDIM; i += 256) {
        int row = i >> 7, col = i & 127;
        int R = R0 + row;
        if (R < 3 * N) g_E[(size_t)R * FDIM + col] = sE[row * 130 + col] + b2[col];
    }
}

// ===========================================================================
// Kernel B: one warp per sample -> distances, triplet loss, L2 sum, hash insert
// ===========================================================================
__global__ __launch_bounds__(256)
void dist_hash_kernel(const int* __restrict__ user0, const int* __restrict__ posi, int N)
{
    int gw = (blockIdx.x * 256 + threadIdx.x) >> 5;
    int l = threadIdx.x & 31;
    float dp = 0.f, dn = 0.f, l2 = 0.f;
    if (gw < N) {
        float4 a = *((const float4*)g_E + (size_t)gw * 32 + l);
        float4 p = *((const float4*)g_E + (size_t)(N + gw) * 32 + l);
        float4 q = *((const float4*)g_E + (size_t)(2 * N + gw) * 32 + l);
        float d;
        d = a.x - p.x; dp += d * d; d = a.y - p.y; dp += d * d;
        d = a.z - p.z; dp += d * d; d = a.w - p.w; dp += d * d;
        d = a.x - q.x; dn += d * d; d = a.y - q.y; dn += d * d;
        d = a.z - q.z; dn += d * d; d = a.w - q.w; dn += d * d;
        l2 += a.x * a.x + a.y * a.y + a.z * a.z + a.w * a.w;
        l2 += p.x * p.x + p.y * p.y + p.z * p.z + p.w * p.w;
        l2 += q.x * q.x + q.y * q.y + q.z * q.z + q.w * q.w;
    }
    #pragma unroll
    for (int s = 16; s >= 1; s >>= 1) {
        dp += __shfl_xor_sync(0xffffffffu, dp, s);
        dn += __shfl_xor_sync(0xffffffffu, dn, s);
        l2 += __shfl_xor_sync(0xffffffffu, l2, s);
    }
    __shared__ float sl2[8];
    if (l == 0) {
        if (gw < N) {
            float lt = fmaxf(dp - dn + 0.5f, 0.f);
            g_lt[gw] = lt;
            ull key = ((ull)(unsigned)user0[gw] << 17) | ((ull)(unsigned)posi[gw]);
            uint32_t slot = (uint32_t)((key * 0x9E3779B97F4A7C15ull) >> 50);
            for (;;) {
                ull old = atomicCAS(&g_hkey[slot], ~0ull, key);
                if (old == ~0ull || old == key) {
                    if (lt > 0.f) atomicAdd(&g_hcnt[slot], 1);
                    g_slot[gw] = (int)slot;
                    break;
                }
                slot = (slot + 1) & (HSLOTS - 1);
            }
        }
        sl2[threadIdx.x >> 5] = l2;
    }
    __syncthreads();
    if (threadIdx.x == 0) {
        float s = 0.f;
        #pragma unroll
        for (int i = 0; i < 8; i++) s += sl2[i];
        atomicAdd(&g_l2sum, s);
    }
}

// ===========================================================================
// Kernel C: weight lookup + weighted loss reduction + last-block finalize
// ===========================================================================
__global__ __launch_bounds__(256)
void weight_finalize_kernel(const int* __restrict__ Jp, const int* __restrict__ Up,
                            int N, float* __restrict__ out)
{
    int i = blockIdx.x * 256 + threadIdx.x;
    float contrib = 0.f;
    if (i < N) {
        int M = g_hcnt[g_slot[i]];
        int J = *Jp, U = *Up;
        float w = (U > 0) ? logf((float)J * (float)M / (float)U + 1.0f) : 0.0f;
        contrib = g_lt[i] * w;
    }
    #pragma unroll
    for (int s = 16; s >= 1; s >>= 1)
        contrib += __shfl_xor_sync(0xffffffffu, contrib, s);
    __shared__ float sw[8];
    if ((threadIdx.x & 31) == 0) sw[threadIdx.x >> 5] = contrib;
    __syncthreads();
    if (threadIdx.x == 0) {
        float s = 0.f;
        #pragma unroll
        for (int k = 0; k < 8; k++) s += sw[k];
        atomicAdd(&g_ltw, s);
        __threadfence();
        int prev = atomicAdd(&g_done, 1);
        if (prev == (int)gridDim.x - 1) {
            float ltw = atomicAdd(&g_ltw, 0.f);
            float l2  = atomicAdd(&g_l2sum, 0.f);
            float ltm = ltw / (float)N;
            out[1] = ltm;
            out[0] = ltm + 1e-3f * l2 / (float)N;
            g_done = 0;
        }
    }
}

// ===========================================================================
extern "C" void kernel_launch(void* const* d_in, const int* in_sizes, int n_in,
                              void* d_out, int out_size)
{
    const int*   user0 = (const int*)d_in[0];
    const int*   posi  = (const int*)d_in[1];
    const int*   negi  = (const int*)d_in[2];
    // d_in[3] = ratings (unused)
    const float* ut = (const float*)d_in[4];
    const float* it = (const float*)d_in[5];
    const float* W1 = (const float*)d_in[6];
    const float* b1 = (const float*)d_in[7];
    const float* ga = (const float*)d_in[8];
    const float* be = (const float*)d_in[9];
    const float* rm = (const float*)d_in[10];
    const float* rv = (const float*)d_in[11];
    const float* W2 = (const float*)d_in[12];
    const float* b2 = (const float*)d_in[13];
    const int*   Jp = (const int*)d_in[14];
    const int*   Up = (const int*)d_in[15];
    int N = in_sizes[0];
    if (N > MAXN) N = MAXN;

    // SMEM: Xs+Hs (64 rows each) + Wa (128 rows) bf16 + bn float2[512] = 73728 B
    const int smemA = (2 * TILE_M + FDIM) * SXB * 2 + HDIM * 8;
    cudaFuncSetAttribute(embed_bf16_kernel, cudaFuncAttributeMaxDynamicSharedMemorySize, smemA);

    int blocksA = (3 * N + TILE_M - 1) / TILE_M;
    embed_bf16_kernel<<<blocksA, 256, smemA>>>(user0, posi, negi, ut, it,
                                               W1, b1, ga, be, rm, rv, W2, b2, N);
    dist_hash_kernel<<<(N + 7) / 8, 256>>>(user0, posi, N);
    weight_finalize_kernel<<<(N + 255) / 256, 256>>>(Jp, Up, N, (float*)d_out);
}

// round 8
// speedup vs baseline: 6.0312x; 1.2599x over previous
#include <cuda_runtime.h>
#include <cuda_bf16.h>
#include <math.h>
#include <stdint.h>

#define MAXN   8192
#define FDIM   128
#define HDIM   512
#define TILE_M 64
#define HSLOTS 16384

#define SXB 136   // bf16 tile row stride (elements); 272B -> ldmatrix conflict-free

typedef unsigned long long ull;

// ---------------- device scratch (no allocations allowed) ------------------
__device__ float g_E[3 * MAXN * FDIM];
__device__ float g_lt[MAXN];
__device__ int   g_slot[MAXN];
__device__ ull   g_hkey[HSLOTS];
__device__ int   g_hcnt[HSLOTS];
__device__ float g_l2sum;
__device__ float g_ltw;
__device__ int   g_done;
// pre-converted bf16 W tiles in LDSM-ready padded layout
__device__ __nv_bfloat16 g_W1t[4][FDIM][SXB];
__device__ __nv_bfloat16 g_W2t[4][FDIM][SXB];

// ---------------- helpers ---------------------------------------------------
__device__ __forceinline__ uint32_t smem_u32(const void* p) {
    uint32_t a;
    asm("{ .reg .u64 t; cvta.to.shared.u64 t, %1; cvt.u32.u64 %0, t; }" : "=r"(a) : "l"(p));
    return a;
}

#define LDSM4(r0, r1, r2, r3, a) \
    asm volatile("ldmatrix.sync.aligned.m8n8.x4.shared.b16 {%0,%1,%2,%3}, [%4];" \
        : "=r"(r0), "=r"(r1), "=r"(r2), "=r"(r3) : "r"(a))

__device__ __forceinline__ void mma_bf16(float c[4],
                                         uint32_t a0, uint32_t a1, uint32_t a2, uint32_t a3,
                                         uint32_t b0, uint32_t b1) {
    asm volatile("mma.sync.aligned.m16n8k16.row.col.f32.bf16.bf16.f32 "
                 "{%0,%1,%2,%3}, {%4,%5,%6,%7}, {%8,%9}, {%0,%1,%2,%3};"
                 : "+f"(c[0]), "+f"(c[1]), "+f"(c[2]), "+f"(c[3])
                 : "r"(a0), "r"(a1), "r"(a2), "r"(a3), "r"(b0), "r"(b1));
}

__device__ __forceinline__ uint32_t pack_bf2(float x, float y) {
    __nv_bfloat162 b = __floats2bfloat162_rn(x, y);
    return *(uint32_t*)&b;
}

__device__ __forceinline__ void cp16(uint32_t dst, const void* src) {
    asm volatile("cp.async.cg.shared.global [%0], [%1], 16;" :: "r"(dst), "l"(src));
}
#define CP_COMMIT() asm volatile("cp.async.commit_group;" ::: "memory")
#define CP_WAIT(n)  asm volatile("cp.async.wait_group %0;" :: "n"(n) : "memory")

// stage one pre-converted 34816B W tile into SMEM via cp.async (issued async)
__device__ __forceinline__ void stage_cp(uint32_t dst, const __nv_bfloat16* src, int tid) {
    const char* s = (const char*)src;
    #pragma unroll
    for (int j = 0; j < 8; j++)
        cp16(dst + tid * 16 + j * 4096, s + tid * 16 + j * 4096);
    if (tid < 128)
        cp16(dst + tid * 16 + 32768, s + tid * 16 + 32768);
    CP_COMMIT();
}

extern __shared__ __nv_bfloat16 s_b[];

// warp-tile GEMM: 16 rows x 64 cols per warp, K=128, bf16 m16n8k16 via ldmatrix
__device__ __forceinline__ void gemm_bf16_tile(float acc[8][4],
                                               uint32_t Aaddr0, uint32_t Baddr0) {
    #pragma unroll
    for (int kt = 0; kt < 8; kt++) {
        const uint32_t ko = kt * 32;       // 16 bf16 = 32 bytes per k-step
        uint32_t a0, a1, a2, a3;
        LDSM4(a0, a1, a2, a3, Aaddr0 + ko);
        uint32_t b[8][2];
        #pragma unroll
        for (int p = 0; p < 4; p++)
            LDSM4(b[2 * p][0], b[2 * p][1], b[2 * p + 1][0], b[2 * p + 1][1],
                  Baddr0 + (uint32_t)p * (16 * SXB * 2) + ko);
        #pragma unroll
        for (int nt = 0; nt < 8; nt++)
            mma_bf16(acc[nt], a0, a1, a2, a3, b[nt][0], b[nt][1]);
    }
}

// ===========================================================================
// Prep kernel: clear hash table + accumulators; convert W1/W2 to bf16 tiles
// grid 64 x 256 = 16384 threads
// ===========================================================================
__global__ __launch_bounds__(256)
void prep_kernel(const float* __restrict__ W1, const float* __restrict__ W2)
{
    int t = blockIdx.x * 256 + threadIdx.x;       // 0..16383
    g_hkey[t] = ~0ull;
    g_hcnt[t] = 0;
    if (t == 0) { g_l2sum = 0.f; g_ltw = 0.f; g_done = 0; }

    int a  = t >> 13;          // 0 = W1, 1 = W2
    int g  = t & 8191;         // 4 chunks * 128 rows * 16 kq
    int c  = g >> 11;
    int r  = (g >> 4) & 127;
    int kq = (g & 15) * 8;
    const float* src = (a == 0)
        ? W1 + ((size_t)(c * FDIM + r)) * FDIM + kq
        : W2 + (size_t)r * HDIM + c * FDIM + kq;
    float4 v0 = ((const float4*)src)[0];
    float4 v1 = ((const float4*)src)[1];
    uint4 o = make_uint4(pack_bf2(v0.x, v0.y), pack_bf2(v0.z, v0.w),
                         pack_bf2(v1.x, v1.y), pack_bf2(v1.z, v1.w));
    __nv_bfloat16* dst = (a == 0) ? &g_W1t[c][r][kq] : &g_W2t[c][r][kq];
    *(uint4*)dst = o;
}

// ===========================================================================
// Kernel A: gather + renorm + Linear/BN/LeakyReLU/Linear, 64 rows per CTA
// cp.async double-buffered W staging: LDG latency off the critical path.
// SMEM: Xs 17.4K + Hs 17.4K + WB0/WB1 34.8K each + bn 4K = 108.5KB, 2 CTAs/SM
// ===========================================================================
__global__ __launch_bounds__(256, 2)
void embed_bf16_kernel(const int* __restrict__ user0, const int* __restrict__ posi,
                       const int* __restrict__ negi,
                       const float* __restrict__ ut, const float* __restrict__ it,
                       const float* __restrict__ b1,
                       const float* __restrict__ gamma1, const float* __restrict__ beta1,
                       const float* __restrict__ rmean, const float* __restrict__ rvar,
                       const float* __restrict__ b2, int N)
{
    const int tid  = threadIdx.x;
    const int wid  = tid >> 5;
    const int lane = tid & 31;
    const int lr   = lane >> 2;      // C-frag row within 16
    const int lq   = lane & 3;       // C-frag col pair
    const int mg   = wid & 3;        // m group: rows mg*16
    const int nh   = wid >> 2;       // n half: cols nh*64

    __nv_bfloat16* Xs  = s_b;                        // 64*SXB   (17408B)
    __nv_bfloat16* Hs  = Xs + TILE_M * SXB;          // 64*SXB   (17408B)
    __nv_bfloat16* WB0 = Hs + TILE_M * SXB;          // 128*SXB  (34816B)
    __nv_bfloat16* WB1 = WB0 + FDIM * SXB;           // 128*SXB  (34816B)
    float2*        bn  = (float2*)(WB1 + FDIM * SXB);
    float*         sE  = (float*)s_b;                // out staging reuses Xs+Hs

    const int R0 = blockIdx.x * TILE_M;
    const uint32_t wb0 = smem_u32(WB0), wb1 = smem_u32(WB1);

    // kick off the first two W stages immediately
    stage_cp(wb0, &g_W1t[0][0][0], tid);
    stage_cp(wb1, &g_W2t[0][0][0], tid);

    // BN consts (fold b1)
    for (int h = tid; h < HDIM; h += 256) {
        float sc = gamma1[h] * rsqrtf(rvar[h] + 1e-5f);
        bn[h] = make_float2(sc, (b1[h] - rmean[h]) * sc + beta1[h]);
    }

    // X: gather + renorm + bf16 (4 threads per row, 32 cols each)
    {
        int row = tid >> 2;
        int q   = tid & 3;
        int R = R0 + row;
        const float* src = nullptr;
        if (R < 3 * N) {
            int g = R / N, n = R - g * N;
            int idx = (g == 0) ? user0[n] : (g == 1 ? posi[n] : negi[n]);
            src = ((g == 0) ? ut : it) + (size_t)idx * FDIM;
        }
        float4 v[8];
        float ss = 0.f;
        #pragma unroll
        for (int j = 0; j < 8; j++) {
            v[j] = src ? ((const float4*)src)[q * 8 + j] : make_float4(0.f, 0.f, 0.f, 0.f);
            ss += v[j].x * v[j].x + v[j].y * v[j].y + v[j].z * v[j].z + v[j].w * v[j].w;
        }
        ss += __shfl_xor_sync(0xffffffffu, ss, 1);
        ss += __shfl_xor_sync(0xffffffffu, ss, 2);
        float inv = 1.0f / fmaxf(sqrtf(ss), 1.0f);
        #pragma unroll
        for (int j = 0; j < 8; j += 2) {
            uint4 o = make_uint4(pack_bf2(v[j].x * inv, v[j].y * inv),
                                 pack_bf2(v[j].z * inv, v[j].w * inv),
                                 pack_bf2(v[j+1].x * inv, v[j+1].y * inv),
                                 pack_bf2(v[j+1].z * inv, v[j+1].w * inv));
            *(uint4*)(Xs + row * SXB + q * 32 + j * 4) = o;
        }
    }

    // per-thread ldmatrix offsets (bytes)
    const int lg = lane >> 3, lw = lane & 7;
    const uint32_t xb = smem_u32(Xs), hb = smem_u32(Hs);
    const uint32_t aoff = (uint32_t)(((mg * 16 + (lg & 1) * 8 + lw) * SXB + (lg >> 1) * 8) * 2);
    const uint32_t boff = (uint32_t)(((nh * 64 + (lg >> 1) * 8 + lw) * SXB + (lg & 1) * 8) * 2);

    float accE[8][4];
    #pragma unroll
    for (int j = 0; j < 8; j++)
        #pragma unroll
        for (int k = 0; k < 4; k++) accE[j][k] = 0.f;

    #pragma unroll 1
    for (int c = 0; c < 4; c++) {
        // ---- GEMM1 chunk c: needs WB0 (group W1_c) + Xs ----
        CP_WAIT(1);                        // W1_c complete (W2_c may be pending)
        __syncthreads();                   // all threads' copies visible + Xs/Hs ready

        float acc1[8][4];
        #pragma unroll
        for (int j = 0; j < 8; j++)
            #pragma unroll
            for (int k = 0; k < 4; k++) acc1[j][k] = 0.f;

        gemm_bf16_tile(acc1, xb + aoff, wb0 + boff);
        __syncthreads();                   // all reads of WB0 done

        if (c < 3) stage_cp(wb0, &g_W1t[c + 1][0][0], tid);   // prefetch next W1

        // BN + LeakyReLU -> Hs (bf16)
        #pragma unroll
        for (int nt = 0; nt < 8; nt++) {
            int row = mg * 16 + lr;
            int col = nh * 64 + nt * 8 + lq * 2;
            float2 p0 = bn[c * FDIM + col];
            float2 p1 = bn[c * FDIM + col + 1];
            float x0 = acc1[nt][0] * p0.x + p0.y;
            float x1 = acc1[nt][1] * p1.x + p1.y;
            float x2 = acc1[nt][2] * p0.x + p0.y;
            float x3 = acc1[nt][3] * p1.x + p1.y;
            x0 = (x0 >= 0.f) ? x0 : 0.1f * x0;
            x1 = (x1 >= 0.f) ? x1 : 0.1f * x1;
            x2 = (x2 >= 0.f) ? x2 : 0.1f * x2;
            x3 = (x3 >= 0.f) ? x3 : 0.1f * x3;
            *(uint32_t*)(Hs + row * SXB + col)       = pack_bf2(x0, x1);
            *(uint32_t*)(Hs + (row + 8) * SXB + col) = pack_bf2(x2, x3);
        }

        // ---- GEMM2 chunk c: needs WB1 (group W2_c) + Hs ----
        if (c < 3) { CP_WAIT(1); }         // pending = W1_{c+1} only -> W2_c done
        else       { CP_WAIT(0); }         // last chunk: drain everything
        __syncthreads();                   // W2_c visible to all + Hs writes visible

        gemm_bf16_tile(accE, hb + aoff, wb1 + boff);
        __syncthreads();                   // all reads of WB1 + Hs done

        if (c < 3) stage_cp(wb1, &g_W2t[c + 1][0][0], tid);   // prefetch next W2
    }

    // E -> padded SMEM -> coalesced global write (+ b2)
    #pragma unroll
    for (int nt = 0; nt < 8; nt++) {
        int row = mg * 16 + lr;
        int col = nh * 64 + nt * 8 + lq * 2;
        *(float2*)(sE + row * 130 + col)       = make_float2(accE[nt][0], accE[nt][1]);
        *(float2*)(sE + (row + 8) * 130 + col) = make_float2(accE[nt][2], accE[nt][3]);
    }
    __syncthreads();
    for (int i = tid; i < TILE_M * FDIM; i += 256) {
        int row = i >> 7, col = i & 127;
        int R = R0 + row;
        if (R < 3 * N) g_E[(size_t)R * FDIM + col] = sE[row * 130 + col] + b2[col];
    }
}

// ===========================================================================
// Kernel B: one warp per sample -> distances, triplet loss, L2 sum, hash insert
// ===========================================================================
__global__ __launch_bounds__(256)
void dist_hash_kernel(const int* __restrict__ user0, const int* __restrict__ posi, int N)
{
    int gw = (blockIdx.x * 256 + threadIdx.x) >> 5;
    int l = threadIdx.x & 31;
    float dp = 0.f, dn = 0.f, l2 = 0.f;
    if (gw < N) {
        float4 a = *((const float4*)g_E + (size_t)gw * 32 + l);
        float4 p = *((const float4*)g_E + (size_t)(N + gw) * 32 + l);
        float4 q = *((const float4*)g_E + (size_t)(2 * N + gw) * 32 + l);
        float d;
        d = a.x - p.x; dp += d * d; d = a.y - p.y; dp += d * d;
        d = a.z - p.z; dp += d * d; d = a.w - p.w; dp += d * d;
        d = a.x - q.x; dn += d * d; d = a.y - q.y; dn += d * d;
        d = a.z - q.z; dn += d * d; d = a.w - q.w; dn += d * d;
        l2 += a.x * a.x + a.y * a.y + a.z * a.z + a.w * a.w;
        l2 += p.x * p.x + p.y * p.y + p.z * p.z + p.w * p.w;
        l2 += q.x * q.x + q.y * q.y + q.z * q.z + q.w * q.w;
    }
    #pragma unroll
    for (int s = 16; s >= 1; s >>= 1) {
        dp += __shfl_xor_sync(0xffffffffu, dp, s);
        dn += __shfl_xor_sync(0xffffffffu, dn, s);
        l2 += __shfl_xor_sync(0xffffffffu, l2, s);
    }
    __shared__ float sl2[8];
    if (l == 0) {
        if (gw < N) {
            float lt = fmaxf(dp - dn + 0.5f, 0.f);
            g_lt[gw] = lt;
            ull key = ((ull)(unsigned)user0[gw] << 17) | ((ull)(unsigned)posi[gw]);
            uint32_t slot = (uint32_t)((key * 0x9E3779B97F4A7C15ull) >> 50);
            for (;;) {
                ull old = atomicCAS(&g_hkey[slot], ~0ull, key);
                if (old == ~0ull || old == key) {
                    if (lt > 0.f) atomicAdd(&g_hcnt[slot], 1);
                    g_slot[gw] = (int)slot;
                    break;
                }
                slot = (slot + 1) & (HSLOTS - 1);
            }
        }
        sl2[threadIdx.x >> 5] = l2;
    }
    __syncthreads();
    if (threadIdx.x == 0) {
        float s = 0.f;
        #pragma unroll
        for (int i = 0; i < 8; i++) s += sl2[i];
        atomicAdd(&g_l2sum, s);
    }
}

// ===========================================================================
// Kernel C: weight lookup + weighted loss reduction + last-block finalize
// ===========================================================================
__global__ __launch_bounds__(256)
void weight_finalize_kernel(const int* __restrict__ Jp, const int* __restrict__ Up,
                            int N, float* __restrict__ out)
{
    int i = blockIdx.x * 256 + threadIdx.x;
    float contrib = 0.f;
    if (i < N) {
        int M = g_hcnt[g_slot[i]];
        int J = *Jp, U = *Up;
        float w = (U > 0) ? logf((float)J * (float)M / (float)U + 1.0f) : 0.0f;
        contrib = g_lt[i] * w;
    }
    #pragma unroll
    for (int s = 16; s >= 1; s >>= 1)
        contrib += __shfl_xor_sync(0xffffffffu, contrib, s);
    __shared__ float sw[8];
    if ((threadIdx.x & 31) == 0) sw[threadIdx.x >> 5] = contrib;
    __syncthreads();
    if (threadIdx.x == 0) {
        float s = 0.f;
        #pragma unroll
        for (int k = 0; k < 8; k++) s += sw[k];
        atomicAdd(&g_ltw, s);
        __threadfence();
        int prev = atomicAdd(&g_done, 1);
        if (prev == (int)gridDim.x - 1) {
            float ltw = atomicAdd(&g_ltw, 0.f);
            float l2  = atomicAdd(&g_l2sum, 0.f);
            float ltm = ltw / (float)N;
            out[1] = ltm;
            out[0] = ltm + 1e-3f * l2 / (float)N;
            g_done = 0;
        }
    }
}

// ===========================================================================
extern "C" void kernel_launch(void* const* d_in, const int* in_sizes, int n_in,
                              void* d_out, int out_size)
{
    const int*   user0 = (const int*)d_in[0];
    const int*   posi  = (const int*)d_in[1];
    const int*   negi  = (const int*)d_in[2];
    // d_in[3] = ratings (unused)
    const float* ut = (const float*)d_in[4];
    const float* it = (const float*)d_in[5];
    const float* W1 = (const float*)d_in[6];
    const float* b1 = (const float*)d_in[7];
    const float* ga = (const float*)d_in[8];
    const float* be = (const float*)d_in[9];
    const float* rm = (const float*)d_in[10];
    const float* rv = (const float*)d_in[11];
    const float* W2 = (const float*)d_in[12];
    const float* b2 = (const float*)d_in[13];
    const int*   Jp = (const int*)d_in[14];
    const int*   Up = (const int*)d_in[15];
    int N = in_sizes[0];
    if (N > MAXN) N = MAXN;

    // SMEM: Xs + Hs (64 rows) + WB0 + WB1 (128 rows) + bn = 108544 B
    const int smemA = (2 * TILE_M + 2 * FDIM) * SXB * 2 + HDIM * 8;
    cudaFuncSetAttribute(embed_bf16_kernel, cudaFuncAttributeMaxDynamicSharedMemorySize, smemA);

    prep_kernel<<<HSLOTS / 256, 256>>>(W1, W2);
    int blocksA = (3 * N + TILE_M - 1) / TILE_M;
    embed_bf16_kernel<<<blocksA, 256, smemA>>>(user0, posi, negi, ut, it,
                                               b1, ga, be, rm, rv, b2, N);
    dist_hash_kernel<<<(N + 7) / 8, 256>>>(user0, posi, N);
    weight_finalize_kernel<<<(N + 255) / 256, 256>>>(Jp, Up, N, (float*)d_out);
}

// round 11
// speedup vs baseline: 6.4470x; 1.0689x over previous
#include <cuda_runtime.h>
#include <cuda_bf16.h>
#include <math.h>
#include <stdint.h>

#define MAXN   8192
#define FDIM   128
#define HDIM   512
#define TILE_M 64
#define HSLOTS 16384

#define SXB 136   // bf16 tile row stride (elements); 272B -> ldmatrix conflict-free

typedef unsigned long long ull;

// ---------------- device scratch (no allocations allowed) ------------------
__device__ float g_E[3 * MAXN * FDIM];
__device__ float g_lt[MAXN];
__device__ int   g_slot[MAXN];
__device__ ull   g_hkey[HSLOTS];
__device__ int   g_hcnt[HSLOTS];
__device__ float g_l2sum;
__device__ float g_ltw;
__device__ int   g_done;
// pre-converted bf16 W tiles in LDSM-ready padded layout
__device__ __nv_bfloat16 g_W1t[4][FDIM][SXB];
__device__ __nv_bfloat16 g_W2t[4][FDIM][SXB];

// ---------------- helpers ---------------------------------------------------
__device__ __forceinline__ uint32_t smem_u32(const void* p) {
    uint32_t a;
    asm("{ .reg .u64 t; cvta.to.shared.u64 t, %1; cvt.u32.u64 %0, t; }" : "=r"(a) : "l"(p));
    return a;
}

#define LDSM4(r0, r1, r2, r3, a) \
    asm volatile("ldmatrix.sync.aligned.m8n8.x4.shared.b16 {%0,%1,%2,%3}, [%4];" \
        : "=r"(r0), "=r"(r1), "=r"(r2), "=r"(r3) : "r"(a))

__device__ __forceinline__ void mma_bf16(float c[4],
                                         uint32_t a0, uint32_t a1, uint32_t a2, uint32_t a3,
                                         uint32_t b0, uint32_t b1) {
    asm volatile("mma.sync.aligned.m16n8k16.row.col.f32.bf16.bf16.f32 "
                 "{%0,%1,%2,%3}, {%4,%5,%6,%7}, {%8,%9}, {%0,%1,%2,%3};"
                 : "+f"(c[0]), "+f"(c[1]), "+f"(c[2]), "+f"(c[3])
                 : "r"(a0), "r"(a1), "r"(a2), "r"(a3), "r"(b0), "r"(b1));
}

__device__ __forceinline__ uint32_t pack_bf2(float x, float y) {
    __nv_bfloat162 b = __floats2bfloat162_rn(x, y);
    return *(uint32_t*)&b;
}

__device__ __forceinline__ void cp16(uint32_t dst, const void* src) {
    asm volatile("cp.async.cg.shared.global [%0], [%1], 16;" :: "r"(dst), "l"(src));
}
#define CP_COMMIT() asm volatile("cp.async.commit_group;" ::: "memory")
#define CP_WAIT(n)  asm volatile("cp.async.wait_group %0;" :: "n"(n) : "memory")

// stage one pre-converted 34816B W tile into SMEM via cp.async (issued async)
__device__ __forceinline__ void stage_cp(uint32_t dst, const __nv_bfloat16* src, int tid) {
    const char* s = (const char*)src;
    #pragma unroll
    for (int j = 0; j < 8; j++)
        cp16(dst + tid * 16 + j * 4096, s + tid * 16 + j * 4096);
    if (tid < 128)
        cp16(dst + tid * 16 + 32768, s + tid * 16 + 32768);
    CP_COMMIT();
}

extern __shared__ __nv_bfloat16 s_b[];

// warp-tile GEMM: 32 rows x 32 cols per warp (2x4 warp grid), K=128
// 4 LDSM per 8 MMA per k-step (was 5 with the 1x8 grid)
__device__ __forceinline__ void gemm_bf16_tile(float acc[2][4][4],
                                               uint32_t Aaddr0, uint32_t Baddr0) {
    #pragma unroll
    for (int kt = 0; kt < 8; kt++) {
        const uint32_t ko = kt * 32;       // 16 bf16 = 32 bytes per k-step
        uint32_t a[2][4];
        LDSM4(a[0][0], a[0][1], a[0][2], a[0][3], Aaddr0 + ko);
        LDSM4(a[1][0], a[1][1], a[1][2], a[1][3], Aaddr0 + 16 * SXB * 2 + ko);
        uint32_t b[4][2];
        LDSM4(b[0][0], b[0][1], b[1][0], b[1][1], Baddr0 + ko);
        LDSM4(b[2][0], b[2][1], b[3][0], b[3][1], Baddr0 + 16 * SXB * 2 + ko);
        #pragma unroll
        for (int mt = 0; mt < 2; mt++)
            #pragma unroll
            for (int nt = 0; nt < 4; nt++)
                mma_bf16(acc[mt][nt], a[mt][0], a[mt][1], a[mt][2], a[mt][3],
                         b[nt][0], b[nt][1]);
    }
}

// ===========================================================================
// Prep kernel: clear hash table + counters; convert W1/W2 to bf16 tiles
// ===========================================================================
__global__ __launch_bounds__(256)
void prep_kernel(const float* __restrict__ W1, const float* __restrict__ W2)
{
    int t = blockIdx.x * 256 + threadIdx.x;       // 0..16383
    g_hkey[t] = ~0ull;
    g_hcnt[t] = 0;
    if (t == 0) { g_l2sum = 0.f; g_ltw = 0.f; g_done = 0; }

    int a  = t >> 13;          // 0 = W1, 1 = W2
    int g  = t & 8191;
    int c  = g >> 11;
    int r  = (g >> 4) & 127;
    int kq = (g & 15) * 8;
    const float* src = (a == 0)
        ? W1 + ((size_t)(c * FDIM + r)) * FDIM + kq
        : W2 + (size_t)r * HDIM + c * FDIM + kq;
    float4 v0 = ((const float4*)src)[0];
    float4 v1 = ((const float4*)src)[1];
    uint4 o = make_uint4(pack_bf2(v0.x, v0.y), pack_bf2(v0.z, v0.w),
                         pack_bf2(v1.x, v1.y), pack_bf2(v1.z, v1.w));
    __nv_bfloat16* dst = (a == 0) ? &g_W1t[c][r][kq] : &g_W2t[c][r][kq];
    *(uint4*)dst = o;
}

// ===========================================================================
// Kernel A: gather + renorm + Linear/BN/LeakyReLU/Linear, 64 rows per CTA
// cp.async double-buffered W staging; 2x4 warp grid (32x32 warp tiles)
// ===========================================================================
__global__ __launch_bounds__(256, 2)
void embed_bf16_kernel(const int* __restrict__ user0, const int* __restrict__ posi,
                       const int* __restrict__ negi,
                       const float* __restrict__ ut, const float* __restrict__ it,
                       const float* __restrict__ b1,
                       const float* __restrict__ gamma1, const float* __restrict__ beta1,
                       const float* __restrict__ rmean, const float* __restrict__ rvar,
                       const float* __restrict__ b2, int N)
{
    const int tid  = threadIdx.x;
    const int wid  = tid >> 5;
    const int lane = tid & 31;
    const int lr   = lane >> 2;      // C-frag row within 16
    const int lq   = lane & 3;       // C-frag col pair
    const int mgg  = wid & 1;        // m group: rows mgg*32
    const int nhh  = wid >> 1;       // n group: cols nhh*32

    __nv_bfloat16* Xs  = s_b;                        // 64*SXB   (17408B)
    __nv_bfloat16* Hs  = Xs + TILE_M * SXB;          // 64*SXB   (17408B)
    __nv_bfloat16* WB0 = Hs + TILE_M * SXB;          // 128*SXB  (34816B)
    __nv_bfloat16* WB1 = WB0 + FDIM * SXB;           // 128*SXB  (34816B)
    float2*        bn  = (float2*)(WB1 + FDIM * SXB);
    float*         sE  = (float*)s_b;                // out staging reuses Xs+Hs

    const int R0 = blockIdx.x * TILE_M;
    const uint32_t wb0 = smem_u32(WB0), wb1 = smem_u32(WB1);

    // kick off the first two W stages immediately
    stage_cp(wb0, &g_W1t[0][0][0], tid);
    stage_cp(wb1, &g_W2t[0][0][0], tid);

    // BN consts (fold b1)
    for (int h = tid; h < HDIM; h += 256) {
        float sc = gamma1[h] * rsqrtf(rvar[h] + 1e-5f);
        bn[h] = make_float2(sc, (b1[h] - rmean[h]) * sc + beta1[h]);
    }

    // X: gather + renorm + bf16 (4 threads per row, 32 cols each)
    {
        int row = tid >> 2;
        int q   = tid & 3;
        int R = R0 + row;
        const float* src = nullptr;
        if (R < 3 * N) {
            int g = R / N, n = R - g * N;
            int idx = (g == 0) ? user0[n] : (g == 1 ? posi[n] : negi[n]);
            src = ((g == 0) ? ut : it) + (size_t)idx * FDIM;
        }
        float4 v[8];
        float ss = 0.f;
        #pragma unroll
        for (int j = 0; j < 8; j++) {
            v[j] = src ? ((const float4*)src)[q * 8 + j] : make_float4(0.f, 0.f, 0.f, 0.f);
            ss += v[j].x * v[j].x + v[j].y * v[j].y + v[j].z * v[j].z + v[j].w * v[j].w;
        }
        ss += __shfl_xor_sync(0xffffffffu, ss, 1);
        ss += __shfl_xor_sync(0xffffffffu, ss, 2);
        float inv = 1.0f / fmaxf(sqrtf(ss), 1.0f);
        #pragma unroll
        for (int j = 0; j < 8; j += 2) {
            uint4 o = make_uint4(pack_bf2(v[j].x * inv, v[j].y * inv),
                                 pack_bf2(v[j].z * inv, v[j].w * inv),
                                 pack_bf2(v[j+1].x * inv, v[j+1].y * inv),
                                 pack_bf2(v[j+1].z * inv, v[j+1].w * inv));
            *(uint4*)(Xs + row * SXB + q * 32 + j * 4) = o;
        }
    }

    // per-thread ldmatrix offsets (bytes)
    const int lg = lane >> 3, lw = lane & 7;
    const uint32_t xb = smem_u32(Xs), hb = smem_u32(Hs);
    const uint32_t aoff = (uint32_t)(((mgg * 32 + (lg & 1) * 8 + lw) * SXB + (lg >> 1) * 8) * 2);
    const uint32_t boff = (uint32_t)(((nhh * 32 + (lg >> 1) * 8 + lw) * SXB + (lg & 1) * 8) * 2);

    float accE[2][4][4];
    #pragma unroll
    for (int i = 0; i < 2; i++)
        #pragma unroll
        for (int j = 0; j < 4; j++)
            #pragma unroll
            for (int k = 0; k < 4; k++) accE[i][j][k] = 0.f;

    #pragma unroll 1
    for (int c = 0; c < 4; c++) {
        // ---- GEMM1 chunk c: needs WB0 (group W1_c) + Xs ----
        CP_WAIT(1);                        // W1_c complete (W2_c may be pending)
        __syncthreads();                   // copies visible + Xs/Hs ready

        float acc1[2][4][4];
        #pragma unroll
        for (int i = 0; i < 2; i++)
            #pragma unroll
            for (int j = 0; j < 4; j++)
                #pragma unroll
                for (int k = 0; k < 4; k++) acc1[i][j][k] = 0.f;

        gemm_bf16_tile(acc1, xb + aoff, wb0 + boff);
        __syncthreads();                   // all reads of WB0 done

        if (c < 3) stage_cp(wb0, &g_W1t[c + 1][0][0], tid);   // prefetch next W1

        // BN + LeakyReLU -> Hs (bf16)
        #pragma unroll
        for (int mt = 0; mt < 2; mt++) {
            #pragma unroll
            for (int nt = 0; nt < 4; nt++) {
                int row = mgg * 32 + mt * 16 + lr;
                int col = nhh * 32 + nt * 8 + lq * 2;
                float2 p0 = bn[c * FDIM + col];
                float2 p1 = bn[c * FDIM + col + 1];
                float x0 = acc1[mt][nt][0] * p0.x + p0.y;
                float x1 = acc1[mt][nt][1] * p1.x + p1.y;
                float x2 = acc1[mt][nt][2] * p0.x + p0.y;
                float x3 = acc1[mt][nt][3] * p1.x + p1.y;
                x0 = (x0 >= 0.f) ? x0 : 0.1f * x0;
                x1 = (x1 >= 0.f) ? x1 : 0.1f * x1;
                x2 = (x2 >= 0.f) ? x2 : 0.1f * x2;
                x3 = (x3 >= 0.f) ? x3 : 0.1f * x3;
                *(uint32_t*)(Hs + row * SXB + col)       = pack_bf2(x0, x1);
                *(uint32_t*)(Hs + (row + 8) * SXB + col) = pack_bf2(x2, x3);
            }
        }

        // ---- GEMM2 chunk c: needs WB1 (group W2_c) + Hs ----
        if (c < 3) { CP_WAIT(1); }         // pending = W1_{c+1} only -> W2_c done
        else       { CP_WAIT(0); }         // last chunk: drain everything
        __syncthreads();                   // W2_c + Hs writes visible

        gemm_bf16_tile(accE, hb + aoff, wb1 + boff);
        __syncthreads();                   // all reads of WB1 + Hs done

        if (c < 3) stage_cp(wb1, &g_W2t[c + 1][0][0], tid);   // prefetch next W2
    }

    // E -> padded SMEM -> coalesced global write (+ b2)
    #pragma unroll
    for (int mt = 0; mt < 2; mt++) {
        #pragma unroll
        for (int nt = 0; nt < 4; nt++) {
            int row = mgg * 32 + mt * 16 + lr;
            int col = nhh * 32 + nt * 8 + lq * 2;
            *(float2*)(sE + row * 130 + col)       = make_float2(accE[mt][nt][0], accE[mt][nt][1]);
            *(float2*)(sE + (row + 8) * 130 + col) = make_float2(accE[mt][nt][2], accE[mt][nt][3]);
        }
    }
    __syncthreads();
    for (int i = tid; i < TILE_M * FDIM; i += 256) {
        int row = i >> 7, col = i & 127;
        int R = R0 + row;
        if (R < 3 * N) g_E[(size_t)R * FDIM + col] = sE[row * 130 + col] + b2[col];
    }
}

// ===========================================================================
// Kernel B: one warp per sample -> distances, triplet loss, L2 sum, hash insert
// ===========================================================================
__global__ __launch_bounds__(256)
void dist_hash_kernel(const int* __restrict__ user0, const int* __restrict__ posi, int N)
{
    int gw = (blockIdx.x * 256 + threadIdx.x) >> 5;
    int l = threadIdx.x & 31;
    float dp = 0.f, dn = 0.f, l2 = 0.f;
    if (gw < N) {
        float4 a = *((const float4*)g_E + (size_t)gw * 32 + l);
        float4 p = *((const float4*)g_E + (size_t)(N + gw) * 32 + l);
        float4 q = *((const float4*)g_E + (size_t)(2 * N + gw) * 32 + l);
        float d;
        d = a.x - p.x; dp += d * d; d = a.y - p.y; dp += d * d;
        d = a.z - p.z; dp += d * d; d = a.w - p.w; dp += d * d;
        d = a.x - q.x; dn += d * d; d = a.y - q.y; dn += d * d;
        d = a.z - q.z; dn += d * d; d = a.w - q.w; dn += d * d;
        l2 += a.x * a.x + a.y * a.y + a.z * a.z + a.w * a.w;
        l2 += p.x * p.x + p.y * p.y + p.z * p.z + p.w * p.w;
        l2 += q.x * q.x + q.y * q.y + q.z * q.z + q.w * q.w;
    }
    #pragma unroll
    for (int s = 16; s >= 1; s >>= 1) {
        dp += __shfl_xor_sync(0xffffffffu, dp, s);
        dn += __shfl_xor_sync(0xffffffffu, dn, s);
        l2 += __shfl_xor_sync(0xffffffffu, l2, s);
    }
    __shared__ float sl2[8];
    if (l == 0) {
        if (gw < N) {
            float lt = fmaxf(dp - dn + 0.5f, 0.f);
            g_lt[gw] = lt;
            ull key = ((ull)(unsigned)user0[gw] << 17) | ((ull)(unsigned)posi[gw]);
            uint32_t slot = (uint32_t)((key * 0x9E3779B97F4A7C15ull) >> 50);
            for (;;) {
                ull old = atomicCAS(&g_hkey[slot], ~0ull, key);
                if (old == ~0ull || old == key) {
                    if (lt > 0.f) atomicAdd(&g_hcnt[slot], 1);
                    g_slot[gw] = (int)slot;
                    break;
                }
                slot = (slot + 1) & (HSLOTS - 1);
            }
        }
        sl2[threadIdx.x >> 5] = l2;
    }
    __syncthreads();
    if (threadIdx.x == 0) {
        float s = 0.f;
        #pragma unroll
        for (int i = 0; i < 8; i++) s += sl2[i];
        atomicAdd(&g_l2sum, s);
    }
}

// ===========================================================================
// Kernel C: weight lookup + weighted loss reduction + last-block finalize
// ===========================================================================
__global__ __launch_bounds__(256)
void weight_finalize_kernel(const int* __restrict__ Jp, const int* __restrict__ Up,
                            int N, float* __restrict__ out)
{
    int i = blockIdx.x * 256 + threadIdx.x;
    float contrib = 0.f;
    if (i < N) {
        int M = g_hcnt[g_slot[i]];
        int J = *Jp, U = *Up;
        float w = (U > 0) ? logf((float)J * (float)M / (float)U + 1.0f) : 0.0f;
        contrib = g_lt[i] * w;
    }
    #pragma unroll
    for (int s = 16; s >= 1; s >>= 1)
        contrib += __shfl_xor_sync(0xffffffffu, contrib, s);
    __shared__ float sw[8];
    if ((threadIdx.x & 31) == 0) sw[threadIdx.x >> 5] = contrib;
    __syncthreads();
    if (threadIdx.x == 0) {
        float s = 0.f;
        #pragma unroll
        for (int k = 0; k < 8; k++) s += sw[k];
        atomicAdd(&g_ltw, s);
        __threadfence();
        int prev = atomicAdd(&g_done, 1);
        if (prev == (int)gridDim.x - 1) {
            float ltw = atomicAdd(&g_ltw, 0.f);
            float l2  = atomicAdd(&g_l2sum, 0.f);
            float ltm = ltw / (float)N;
            out[1] = ltm;
            out[0] = ltm + 1e-3f * l2 / (float)N;
            g_done = 0;
        }
    }
}

// ===========================================================================
extern "C" void kernel_launch(void* const* d_in, const int* in_sizes, int n_in,
                              void* d_out, int out_size)
{
    const int*   user0 = (const int*)d_in[0];
    const int*   posi  = (const int*)d_in[1];
    const int*   negi  = (const int*)d_in[2];
    // d_in[3] = ratings (unused)
    const float* ut = (const float*)d_in[4];
    const float* it = (const float*)d_in[5];
    const float* W1 = (const float*)d_in[6];
    const float* b1 = (const float*)d_in[7];
    const float* ga = (const float*)d_in[8];
    const float* be = (const float*)d_in[9];
    const float* rm = (const float*)d_in[10];
    const float* rv = (const float*)d_in[11];
    const float* W2 = (const float*)d_in[12];
    const float* b2 = (const float*)d_in[13];
    const int*   Jp = (const int*)d_in[14];
    const int*   Up = (const int*)d_in[15];
    int N = in_sizes[0];
    if (N > MAXN) N = MAXN;

    // SMEM: Xs + Hs (64 rows) + WB0 + WB1 (128 rows) + bn = 108544 B
    const int smemA = (2 * TILE_M + 2 * FDIM) * SXB * 2 + HDIM * 8;
    cudaFuncSetAttribute(embed_bf16_kernel, cudaFuncAttributeMaxDynamicSharedMemorySize, smemA);

    prep_kernel<<<HSLOTS / 256, 256>>>(W1, W2);
    int blocksA = (3 * N + TILE_M - 1) / TILE_M;
    embed_bf16_kernel<<<blocksA, 256, smemA>>>(user0, posi, negi, ut, it,
                                               b1, ga, be, rm, rv, b2, N);
    dist_hash_kernel<<<(N + 7) / 8, 256>>>(user0, posi, N);
    weight_finalize_kernel<<<(N + 255) / 256, 256>>>(Jp, Up, N, (float*)d_out);
}